// round 1
// baseline (speedup 1.0000x reference)
#include <cuda_runtime.h>
#include <math.h>

#define BB 1024
#define TT 512
#define CTXN 23
#define DD 320
#define LL 5
#define HH 8
#define FFN 1280
#define NM 49      // NMODES+1
#define SS 24      // CLS + 23 tokens
#define DHD 40
#define NTHREADS 320

// Per-batch Chebyshev coefficients produced by the transformer head.
__device__ float g_c[BB * NM];

// SMEM layout (floats):
//   x       [0, 7680)           24*320 residual stream
//   hbuf    [7680, 15360)       24*320 LN output / attn output
//   scratch [15360, 46080)      24*1280 (qkv uses 24*960; FFN hidden uses all)
//   scores  [46080, 50688)      8*24*24 attention probs
#define SM_X       0
#define SM_HBUF    7680
#define SM_SCRATCH 15360
#define SM_SCORES  46080
#define SMEM_FLOATS 50688
#define SMEM_BYTES (SMEM_FLOATS * 4)

// C[s, j] = act( sum_k A[s,k] * W[j,k] + bias[j] ), optionally accumulated into C.
// A: SMEM, row stride K. W: global row-major [N, K]. C: SMEM, row stride N.
template<int ACT, int ACC>
__device__ __forceinline__ void matmul_sw(const float* __restrict__ A,
                                          const float* __restrict__ W,
                                          const float* __restrict__ bias,
                                          float* __restrict__ C,
                                          int K, int N)
{
    const int K4 = K >> 2;
    for (int j = threadIdx.x; j < N; j += NTHREADS) {
        float acc[SS];
        #pragma unroll
        for (int s = 0; s < SS; s++) acc[s] = 0.f;
        const float4* __restrict__ Wr = (const float4*)(W + (size_t)j * K);
        for (int k4 = 0; k4 < K4; k4++) {
            float4 w = Wr[k4];
            #pragma unroll
            for (int s = 0; s < SS; s++) {
                float4 a = ((const float4*)(A + s * K))[k4];
                acc[s] += a.x * w.x;
                acc[s] += a.y * w.y;
                acc[s] += a.z * w.z;
                acc[s] += a.w * w.w;
            }
        }
        float bj = bias[j];
        #pragma unroll
        for (int s = 0; s < SS; s++) {
            float v = acc[s] + bj;
            if (ACT == 1) v = 0.5f * v * (1.f + erff(v * 0.70710678118654752f));
            if (ACC == 1) C[s * N + j] += v;
            else          C[s * N + j] = v;
        }
    }
}

// LayerNorm of 24 rows of length 320: OUT[s,:] = (X[s,:]-m)*rsqrt(v+eps)*w + b
__device__ __forceinline__ void layernorm_rows(const float* __restrict__ X,
                                               const float* __restrict__ w,
                                               const float* __restrict__ b,
                                               float* __restrict__ OUT)
{
    int wid = threadIdx.x >> 5, lane = threadIdx.x & 31;
    for (int s = wid; s < SS; s += NTHREADS / 32) {
        const float* row = X + s * DD;
        float sum = 0.f, sq = 0.f;
        #pragma unroll
        for (int k = lane; k < DD; k += 32) { float v = row[k]; sum += v; sq += v * v; }
        #pragma unroll
        for (int o = 16; o > 0; o >>= 1) {
            sum += __shfl_xor_sync(0xffffffffu, sum, o);
            sq  += __shfl_xor_sync(0xffffffffu, sq, o);
        }
        float mean = sum * (1.f / DD);
        float var = sq * (1.f / DD) - mean * mean;
        float inv = rsqrtf(var + 1e-5f);
        #pragma unroll
        for (int k = lane; k < DD; k += 32)
            OUT[s * DD + k] = (row[k] - mean) * inv * w[k] + b[k];
    }
}

__global__ void __launch_bounds__(NTHREADS, 1)
transformer_kernel(const float* __restrict__ ctx,
                   const float* __restrict__ W_e,  const float* __restrict__ b_e,
                   const float* __restrict__ cls,
                   const float* __restrict__ ln1_w, const float* __restrict__ ln1_b,
                   const float* __restrict__ W_in,  const float* __restrict__ b_in,
                   const float* __restrict__ W_out, const float* __restrict__ b_out,
                   const float* __restrict__ ln2_w, const float* __restrict__ ln2_b,
                   const float* __restrict__ W1,    const float* __restrict__ b1,
                   const float* __restrict__ W2,    const float* __restrict__ b2,
                   const float* __restrict__ hln_w, const float* __restrict__ hln_b,
                   const float* __restrict__ Wh1,   const float* __restrict__ bh1,
                   const float* __restrict__ Wh2,   const float* __restrict__ bh2)
{
    extern __shared__ float sm[];
    float* x       = sm + SM_X;
    float* hbuf    = sm + SM_HBUF;
    float* scratch = sm + SM_SCRATCH;
    float* scores  = sm + SM_SCORES;

    const int b   = blockIdx.x;
    const int tid = threadIdx.x;

    // ---- embedding: x[0] = cls; x[1+t] = ctx[b,t]*W_e + b_e ----
    for (int i = tid; i < SS * DD; i += NTHREADS) {
        int s = i / DD, d = i - s * DD;
        float v;
        if (s == 0) v = cls[d];
        else        v = ctx[b * CTXN + (s - 1)] * W_e[d] + b_e[d];
        x[i] = v;
    }
    __syncthreads();

    for (int l = 0; l < LL; l++) {
        // ---- pre-norm attention ----
        layernorm_rows(x, ln1_w + l * DD, ln1_b + l * DD, hbuf);
        __syncthreads();
        matmul_sw<0, 0>(hbuf, W_in + (size_t)l * 3 * DD * DD, b_in + l * 3 * DD,
                        scratch, DD, 3 * DD);   // qkv (24 x 960)
        __syncthreads();

        // scores[h][i][j] = q_i . k_j / sqrt(DH)
        for (int idx = tid; idx < HH * SS * SS; idx += NTHREADS) {
            int h   = idx / (SS * SS);
            int rem = idx - h * (SS * SS);
            int i   = rem / SS, j = rem - i * SS;
            const float* q = scratch + i * (3 * DD) + h * DHD;
            const float* k = scratch + j * (3 * DD) + DD + h * DHD;
            float s2 = 0.f;
            #pragma unroll
            for (int d = 0; d < DHD; d++) s2 += q[d] * k[d];
            scores[idx] = s2 * 0.15811388300841897f;  // 1/sqrt(40)
        }
        __syncthreads();

        // softmax over j, one thread per (h,i) row
        for (int r = tid; r < HH * SS; r += NTHREADS) {
            float* row = scores + r * SS;
            float mx = row[0];
            #pragma unroll
            for (int j = 1; j < SS; j++) mx = fmaxf(mx, row[j]);
            float sum = 0.f;
            #pragma unroll
            for (int j = 0; j < SS; j++) { float e = expf(row[j] - mx); row[j] = e; sum += e; }
            float inv = 1.f / sum;
            #pragma unroll
            for (int j = 0; j < SS; j++) row[j] *= inv;
        }
        __syncthreads();

        // o[i, d] = sum_j a[h(d), i, j] * v[j, d]
        for (int idx = tid; idx < SS * DD; idx += NTHREADS) {
            int i = idx / DD, d = idx - i * DD;
            int h = d / DHD;
            const float* arow = scores + (h * SS + i) * SS;
            float acc = 0.f;
            #pragma unroll
            for (int j = 0; j < SS; j++)
                acc += arow[j] * scratch[j * (3 * DD) + 2 * DD + d];
            hbuf[idx] = acc;
        }
        __syncthreads();
        matmul_sw<0, 1>(hbuf, W_out + (size_t)l * DD * DD, b_out + l * DD, x, DD, DD);
        __syncthreads();

        // ---- pre-norm FFN ----
        layernorm_rows(x, ln2_w + l * DD, ln2_b + l * DD, hbuf);
        __syncthreads();
        matmul_sw<1, 0>(hbuf, W1 + (size_t)l * FFN * DD, b1 + l * FFN, scratch, DD, FFN);
        __syncthreads();
        matmul_sw<0, 1>(scratch, W2 + (size_t)l * DD * FFN, b2 + l * DD, x, FFN, DD);
        __syncthreads();
    }

    // ---- head: LN(x[0]) -> gelu(@Wh1.T+bh1) -> @Wh2.T+bh2 -> g_c[b] ----
    {
        __shared__ float wsum[NTHREADS / 32], wsq[NTHREADS / 32], red[2];
        float v = x[tid];                // tid in [0,320) == DD
        float sum = v, sq = v * v;
        #pragma unroll
        for (int o = 16; o > 0; o >>= 1) {
            sum += __shfl_xor_sync(0xffffffffu, sum, o);
            sq  += __shfl_xor_sync(0xffffffffu, sq, o);
        }
        int wid = tid >> 5, lane = tid & 31;
        if (lane == 0) { wsum[wid] = sum; wsq[wid] = sq; }
        __syncthreads();
        if (tid == 0) {
            float s = 0.f, q = 0.f;
            #pragma unroll
            for (int w2 = 0; w2 < NTHREADS / 32; w2++) { s += wsum[w2]; q += wsq[w2]; }
            float mean = s * (1.f / DD);
            float var = q * (1.f / DD) - mean * mean;
            red[0] = mean; red[1] = rsqrtf(var + 1e-5f);
        }
        __syncthreads();
        hbuf[tid] = (x[tid] - red[0]) * red[1] * hln_w[tid] + hln_b[tid];
        __syncthreads();

        // hidden = gelu(h @ Wh1.T + bh1), one thread per output
        {
            int j = tid;
            const float4* Wr = (const float4*)(Wh1 + (size_t)j * DD);
            float acc = 0.f;
            #pragma unroll 4
            for (int k4 = 0; k4 < DD / 4; k4++) {
                float4 w = Wr[k4];
                float4 a = ((const float4*)hbuf)[k4];
                acc += a.x * w.x + a.y * w.y + a.z * w.z + a.w * w.w;
            }
            acc += bh1[j];
            scratch[j] = 0.5f * acc * (1.f + erff(acc * 0.70710678118654752f));
        }
        __syncthreads();

        if (tid < NM) {
            const float4* Wr = (const float4*)(Wh2 + (size_t)tid * DD);
            float acc = 0.f;
            #pragma unroll 4
            for (int k4 = 0; k4 < DD / 4; k4++) {
                float4 w = Wr[k4];
                float4 a = ((const float4*)scratch)[k4];
                acc += a.x * w.x + a.y * w.y + a.z * w.z + a.w * w.w;
            }
            g_c[b * NM + tid] = acc + bh2[tid];
        }
    }
}

// z = sum_n c[b,n] * T_n(k_norm), out = sigmoid(z). Block covers 256 t's of one b.
__global__ void __launch_bounds__(256)
cheb_kernel(const float* __restrict__ k_norm, float* __restrict__ out)
{
    __shared__ float c[NM];
    const int b = blockIdx.x >> 1;
    const int t = ((blockIdx.x & 1) << 8) + threadIdx.x;
    if (threadIdx.x < NM) c[threadIdx.x] = g_c[b * NM + threadIdx.x];
    __syncthreads();
    float xx = k_norm[b * TT + t];
    float tp = 1.f, tc = xx;
    float acc = c[0] + c[1] * xx;
    float x2 = 2.f * xx;
    #pragma unroll
    for (int n = 2; n < NM; n++) {
        float tn = x2 * tc - tp;
        acc += c[n] * tn;
        tp = tc; tc = tn;
    }
    out[b * TT + t] = 1.f / (1.f + expf(-acc));
}

extern "C" void kernel_launch(void* const* d_in, const int* in_sizes, int n_in,
                              void* d_out, int out_size)
{
    const float* k_norm = (const float*)d_in[0];
    const float* ctx    = (const float*)d_in[1];
    const float* W_e    = (const float*)d_in[2];
    const float* b_e    = (const float*)d_in[3];
    const float* cls    = (const float*)d_in[4];
    const float* ln1_w  = (const float*)d_in[5];
    const float* ln1_b  = (const float*)d_in[6];
    const float* W_in   = (const float*)d_in[7];
    const float* b_in   = (const float*)d_in[8];
    const float* W_out  = (const float*)d_in[9];
    const float* b_out  = (const float*)d_in[10];
    const float* ln2_w  = (const float*)d_in[11];
    const float* ln2_b  = (const float*)d_in[12];
    const float* W1     = (const float*)d_in[13];
    const float* b1     = (const float*)d_in[14];
    const float* W2     = (const float*)d_in[15];
    const float* b2     = (const float*)d_in[16];
    const float* hln_w  = (const float*)d_in[17];
    const float* hln_b  = (const float*)d_in[18];
    const float* Wh1    = (const float*)d_in[19];
    const float* bh1    = (const float*)d_in[20];
    const float* Wh2    = (const float*)d_in[21];
    const float* bh2    = (const float*)d_in[22];

    cudaFuncSetAttribute(transformer_kernel,
                         cudaFuncAttributeMaxDynamicSharedMemorySize, SMEM_BYTES);

    transformer_kernel<<<BB, NTHREADS, SMEM_BYTES>>>(
        ctx, W_e, b_e, cls, ln1_w, ln1_b, W_in, b_in, W_out, b_out,
        ln2_w, ln2_b, W1, b1, W2, b2, hln_w, hln_b, Wh1, bh1, Wh2, bh2);

    cheb_kernel<<<BB * 2, 256>>>(k_norm, (float*)d_out);
}

// round 3
// speedup vs baseline: 2.7671x; 2.7671x over previous
#include <cuda_runtime.h>
#include <math.h>
#include <stdint.h>
#include <mma.h>

using namespace nvcuda;

#define BB 1024
#define TT 512
#define CTXN 23
#define DD 320
#define LL 5
#define HH 8
#define FFN 1280
#define NM 49      // NMODES+1
#define SS 24      // CLS + 23 tokens
#define DHD 40
#define MTOT (BB * SS)   // 24576

// ------------------------------------------------------------------
// Global scratch
// ------------------------------------------------------------------
__device__ float g_x[MTOT * DD];      // residual stream
__device__ float g_h[MTOT * DD];      // LN output / attn output
__device__ float g_big[MTOT * FFN];   // qkv (960 cols) / ffn hidden
__device__ float g_c[BB * NM];        // chebyshev coefficients

__device__ __forceinline__ uint32_t smem_u32(const void* p) {
    uint32_t a;
    asm("{ .reg .u64 t; cvta.to.shared.u64 t, %1; cvt.u32.u64 %0, t; }"
        : "=r"(a) : "l"(p));
    return a;
}
__device__ __forceinline__ void cp_async16(uint32_t s, const void* g) {
    asm volatile("cp.async.cg.shared.global [%0], [%1], 16;" :: "r"(s), "l"(g));
}
#define CP_COMMIT() asm volatile("cp.async.commit_group;" ::: "memory")
#define CP_WAIT(n)  asm volatile("cp.async.wait_group %0;" :: "n"(n) : "memory")

// ------------------------------------------------------------------
// wmma tf32 GEMM:  C[m,n] = act( A[m,:].B[n,:] + bias[n] ) (+ R[m,n])
// A: [M, K] row-major.  B: [N, K] row-major.  Tiles: BM x BN x BK.
// ------------------------------------------------------------------
#define BM 128
#define BN 64
#define BK 32
#define ASTR 36            // padded row stride (floats), 144B (16B-aligned)
#define BSTR 36
#define CSTR 68            // epilogue staging stride
#define A_BUF (BM * ASTR)  // floats
#define B_BUF (BN * BSTR)
#define GSM_FLOATS (2 * A_BUF + 2 * B_BUF)   // 13824 floats = 55296 B
#define GSM_BYTES (GSM_FLOATS * 4)

template<int ACT, int RES>
__global__ void __launch_bounds__(256)
gemm_wmma(const float* __restrict__ A, const float* __restrict__ B,
          const float* __restrict__ bias, const float* __restrict__ R,
          float* __restrict__ C, int K, int N)
{
    extern __shared__ float sm[];
    float* As = sm;                  // [2][BM][ASTR]
    float* Bs = sm + 2 * A_BUF;      // [2][BN][BSTR]

    const int tid = threadIdx.x;
    const int wid = tid >> 5;
    const int wm = wid & 3;          // warp row 0..3  (32 rows each)
    const int wn = wid >> 2;         // warp col 0..1  (32 cols each)
    const int mbase = blockIdx.x * BM;
    const int nbase = blockIdx.y * BN;
    const int KT = K / BK;

    wmma::fragment<wmma::accumulator, 16, 16, 8, float> acc[2][2];
    #pragma unroll
    for (int i = 0; i < 2; i++)
        #pragma unroll
        for (int j = 0; j < 2; j++) wmma::fill_fragment(acc[i][j], 0.0f);

    // cp.async tile loaders
    // A: 128x32 floats = 1024 float4, 4 per thread. row = idx/8, c4 = idx%8.
    // B:  64x32 floats =  512 float4, 2 per thread.
    uint32_t sA = smem_u32(As);
    uint32_t sB = smem_u32(Bs);

    auto load_tile = [&](int kt, int buf) {
        const float* Ag = A + (size_t)mbase * K + kt * BK;
        const float* Bg = B + (size_t)nbase * K + kt * BK;
        #pragma unroll
        for (int t = 0; t < 4; t++) {
            int idx = t * 256 + tid;
            int row = idx >> 3, c4 = idx & 7;
            cp_async16(sA + (uint32_t)(buf * A_BUF + row * ASTR + c4 * 4) * 4,
                       Ag + (size_t)row * K + c4 * 4);
        }
        #pragma unroll
        for (int t = 0; t < 2; t++) {
            int idx = t * 256 + tid;
            int row = idx >> 3, c4 = idx & 7;
            cp_async16(sB + (uint32_t)(buf * B_BUF + row * BSTR + c4 * 4) * 4,
                       Bg + (size_t)row * K + c4 * 4);
        }
        CP_COMMIT();
    };

    load_tile(0, 0);

    for (int kt = 0; kt < KT; kt++) {
        const int cur = kt & 1;
        if (kt + 1 < KT) { load_tile(kt + 1, 1 - cur); CP_WAIT(1); }
        else             { CP_WAIT(0); }
        __syncthreads();

        const float* Ab = As + cur * A_BUF + wm * 32 * ASTR;
        const float* Bb = Bs + cur * B_BUF + wn * 32 * BSTR;
        #pragma unroll
        for (int k0 = 0; k0 < BK; k0 += 8) {
            wmma::fragment<wmma::matrix_a, 16, 16, 8, wmma::precision::tf32,
                           wmma::row_major> af[2];
            wmma::fragment<wmma::matrix_b, 16, 16, 8, wmma::precision::tf32,
                           wmma::col_major> bf[2];
            #pragma unroll
            for (int i = 0; i < 2; i++) {
                wmma::load_matrix_sync(af[i], Ab + i * 16 * ASTR + k0, ASTR);
                #pragma unroll
                for (int e = 0; e < af[i].num_elements; e++)
                    af[i].x[e] = wmma::__float_to_tf32(af[i].x[e]);
            }
            #pragma unroll
            for (int j = 0; j < 2; j++) {
                wmma::load_matrix_sync(bf[j], Bb + j * 16 * BSTR + k0, BSTR);
                #pragma unroll
                for (int e = 0; e < bf[j].num_elements; e++)
                    bf[j].x[e] = wmma::__float_to_tf32(bf[j].x[e]);
            }
            #pragma unroll
            for (int i = 0; i < 2; i++)
                #pragma unroll
                for (int j = 0; j < 2; j++)
                    wmma::mma_sync(acc[i][j], af[i], bf[j], acc[i][j]);
        }
        __syncthreads();
    }

    // epilogue: stage accumulators in SMEM, fuse bias/act/residual
    float* Cs = sm;   // 128 x CSTR
    #pragma unroll
    for (int i = 0; i < 2; i++)
        #pragma unroll
        for (int j = 0; j < 2; j++)
            wmma::store_matrix_sync(Cs + (wm * 32 + i * 16) * CSTR + wn * 32 + j * 16,
                                    acc[i][j], CSTR, wmma::mem_row_major);
    __syncthreads();

    #pragma unroll 4
    for (int idx = tid; idx < BM * BN; idx += 256) {
        int r = idx >> 6, c = idx & 63;
        float v = Cs[r * CSTR + c] + bias[nbase + c];
        if (ACT) v = 0.5f * v * (1.f + erff(v * 0.70710678118654752f));
        size_t gi = (size_t)(mbase + r) * N + nbase + c;
        if (RES) v += R[gi];
        C[gi] = v;
    }
}

// ------------------------------------------------------------------
// Elementwise / small kernels
// ------------------------------------------------------------------
__global__ void __launch_bounds__(256)
embed_kernel(const float* __restrict__ ctx, const float* __restrict__ W_e,
             const float* __restrict__ b_e, const float* __restrict__ cls,
             float* __restrict__ X)
{
    int i = blockIdx.x * 256 + threadIdx.x;
    int d = i % DD;
    int s = (i / DD) % SS;
    int b = i / (DD * SS);
    float v;
    if (s == 0) v = cls[d];
    else        v = ctx[b * CTXN + (s - 1)] * W_e[d] + b_e[d];
    X[i] = v;
}

// one warp per row of 320
__global__ void __launch_bounds__(256)
ln_kernel(const float* __restrict__ X, const float* __restrict__ w,
          const float* __restrict__ b, float* __restrict__ O)
{
    int row = blockIdx.x * 8 + (threadIdx.x >> 5);
    int lane = threadIdx.x & 31;
    const float* xr = X + (size_t)row * DD;
    float sum = 0.f, sq = 0.f;
    #pragma unroll
    for (int k = lane; k < DD; k += 32) { float v = xr[k]; sum += v; sq += v * v; }
    #pragma unroll
    for (int o = 16; o > 0; o >>= 1) {
        sum += __shfl_xor_sync(0xffffffffu, sum, o);
        sq  += __shfl_xor_sync(0xffffffffu, sq, o);
    }
    float mean = sum * (1.f / DD);
    float var  = sq * (1.f / DD) - mean * mean;
    float inv  = rsqrtf(var + 1e-5f);
    float* orow = O + (size_t)row * DD;
    #pragma unroll
    for (int k = lane; k < DD; k += 32)
        orow[k] = (xr[k] - mean) * inv * w[k] + b[k];
}

// attention for one batch element: qkv rows [b*24, b*24+24) of [*, 960]
#define QST 964   // padded smem row stride (floats)
#define ATTN_SMEM ((SS * QST + HH * SS * SS) * 4)
__global__ void __launch_bounds__(256)
attn_kernel(const float* __restrict__ qkv, float* __restrict__ o)
{
    extern __shared__ float smf[];
    float* t  = smf;             // [24][QST]: q 0-319, k 320-639, v 640-959
    float* sc = smf + SS * QST;  // [8*24*24]
    const int b = blockIdx.x, tid = threadIdx.x;

    const float4* src = (const float4*)(qkv + (size_t)b * SS * 960);
    for (int i = tid; i < SS * 240; i += 256) {
        int r = i / 240, c = i - r * 240;
        ((float4*)(t + r * QST))[c] = src[r * 240 + c];
    }
    __syncthreads();

    for (int idx = tid; idx < HH * SS * SS; idx += 256) {
        int h = idx / (SS * SS);
        int rem = idx - h * (SS * SS);
        int i = rem / SS, j = rem - i * SS;
        const float* q = t + i * QST + h * DHD;
        const float* k = t + j * QST + DD + h * DHD;
        float s = 0.f;
        #pragma unroll
        for (int d = 0; d < DHD; d += 4)
            s += q[d] * k[d] + q[d+1] * k[d+1] + q[d+2] * k[d+2] + q[d+3] * k[d+3];
        sc[idx] = s * 0.15811388300841897f;   // 1/sqrt(40)
    }
    __syncthreads();

    if (tid < HH * SS) {
        float* row = sc + tid * SS;
        float mx = row[0];
        #pragma unroll
        for (int j = 1; j < SS; j++) mx = fmaxf(mx, row[j]);
        float sum = 0.f;
        #pragma unroll
        for (int j = 0; j < SS; j++) { float e = expf(row[j] - mx); row[j] = e; sum += e; }
        float inv = 1.f / sum;
        #pragma unroll
        for (int j = 0; j < SS; j++) row[j] *= inv;
    }
    __syncthreads();

    for (int idx = tid; idx < SS * DD; idx += 256) {
        int i = idx / DD, d = idx - i * DD;
        int h = d / DHD;
        const float* a = sc + (h * SS + i) * SS;
        float acc = 0.f;
        #pragma unroll
        for (int j = 0; j < SS; j++) acc += a[j] * t[j * QST + 2 * DD + d];
        o[(size_t)(b * SS + i) * DD + d] = acc;
    }
}

// CLS head: LN -> gelu(Wh1) -> Wh2 -> g_c
__global__ void __launch_bounds__(320)
head_kernel(const float* __restrict__ X,
            const float* __restrict__ hln_w, const float* __restrict__ hln_b,
            const float* __restrict__ Wh1,   const float* __restrict__ bh1,
            const float* __restrict__ Wh2,   const float* __restrict__ bh2)
{
    __shared__ float hbuf[DD], scr[DD], wsum[10], wsq[10], red[2];
    const int b = blockIdx.x, tid = threadIdx.x;
    const float* xr = X + (size_t)b * SS * DD;   // CLS row

    float v = xr[tid];
    float sum = v, sq = v * v;
    #pragma unroll
    for (int o = 16; o > 0; o >>= 1) {
        sum += __shfl_xor_sync(0xffffffffu, sum, o);
        sq  += __shfl_xor_sync(0xffffffffu, sq, o);
    }
    int wid = tid >> 5, lane = tid & 31;
    if (lane == 0) { wsum[wid] = sum; wsq[wid] = sq; }
    __syncthreads();
    if (tid == 0) {
        float s = 0.f, q = 0.f;
        #pragma unroll
        for (int w = 0; w < 10; w++) { s += wsum[w]; q += wsq[w]; }
        float mean = s * (1.f / DD);
        float var  = q * (1.f / DD) - mean * mean;
        red[0] = mean; red[1] = rsqrtf(var + 1e-5f);
    }
    __syncthreads();
    hbuf[tid] = (v - red[0]) * red[1] * hln_w[tid] + hln_b[tid];
    __syncthreads();

    {
        const float4* Wr = (const float4*)(Wh1 + (size_t)tid * DD);
        float acc = 0.f;
        #pragma unroll 4
        for (int k4 = 0; k4 < DD / 4; k4++) {
            float4 w = Wr[k4];
            float4 a = ((const float4*)hbuf)[k4];
            acc += a.x * w.x + a.y * w.y + a.z * w.z + a.w * w.w;
        }
        acc += bh1[tid];
        scr[tid] = 0.5f * acc * (1.f + erff(acc * 0.70710678118654752f));
    }
    __syncthreads();

    if (tid < NM) {
        const float4* Wr = (const float4*)(Wh2 + (size_t)tid * DD);
        float acc = 0.f;
        #pragma unroll 4
        for (int k4 = 0; k4 < DD / 4; k4++) {
            float4 w = Wr[k4];
            float4 a = ((const float4*)scr)[k4];
            acc += a.x * w.x + a.y * w.y + a.z * w.z + a.w * w.w;
        }
        g_c[b * NM + tid] = acc + bh2[tid];
    }
}

__global__ void __launch_bounds__(256)
cheb_kernel(const float* __restrict__ k_norm, float* __restrict__ out)
{
    __shared__ float c[NM];
    const int b = blockIdx.x >> 1;
    const int t = ((blockIdx.x & 1) << 8) + threadIdx.x;
    if (threadIdx.x < NM) c[threadIdx.x] = g_c[b * NM + threadIdx.x];
    __syncthreads();
    float xx = k_norm[b * TT + t];
    float tp = 1.f, tc = xx;
    float acc = c[0] + c[1] * xx;
    float x2 = 2.f * xx;
    #pragma unroll
    for (int n = 2; n < NM; n++) {
        float tn = x2 * tc - tp;
        acc += c[n] * tn;
        tp = tc; tc = tn;
    }
    out[b * TT + t] = 1.f / (1.f + expf(-acc));
}

// ------------------------------------------------------------------
// Host
// ------------------------------------------------------------------
extern "C" void kernel_launch(void* const* d_in, const int* in_sizes, int n_in,
                              void* d_out, int out_size)
{
    const float* k_norm = (const float*)d_in[0];
    const float* ctx    = (const float*)d_in[1];
    const float* W_e    = (const float*)d_in[2];
    const float* b_e    = (const float*)d_in[3];
    const float* cls    = (const float*)d_in[4];
    const float* ln1_w  = (const float*)d_in[5];
    const float* ln1_b  = (const float*)d_in[6];
    const float* W_in   = (const float*)d_in[7];
    const float* b_in   = (const float*)d_in[8];
    const float* W_out  = (const float*)d_in[9];
    const float* b_out  = (const float*)d_in[10];
    const float* ln2_w  = (const float*)d_in[11];
    const float* ln2_b  = (const float*)d_in[12];
    const float* W1     = (const float*)d_in[13];
    const float* b1     = (const float*)d_in[14];
    const float* W2     = (const float*)d_in[15];
    const float* b2     = (const float*)d_in[16];
    const float* hln_w  = (const float*)d_in[17];
    const float* hln_b  = (const float*)d_in[18];
    const float* Wh1    = (const float*)d_in[19];
    const float* bh1    = (const float*)d_in[20];
    const float* Wh2    = (const float*)d_in[21];
    const float* bh2    = (const float*)d_in[22];

    float *px, *ph, *pbig;
    cudaGetSymbolAddress((void**)&px,   g_x);
    cudaGetSymbolAddress((void**)&ph,   g_h);
    cudaGetSymbolAddress((void**)&pbig, g_big);

    cudaFuncSetAttribute(gemm_wmma<0,0>, cudaFuncAttributeMaxDynamicSharedMemorySize, GSM_BYTES);
    cudaFuncSetAttribute(gemm_wmma<0,1>, cudaFuncAttributeMaxDynamicSharedMemorySize, GSM_BYTES);
    cudaFuncSetAttribute(gemm_wmma<1,0>, cudaFuncAttributeMaxDynamicSharedMemorySize, GSM_BYTES);
    cudaFuncSetAttribute(attn_kernel,    cudaFuncAttributeMaxDynamicSharedMemorySize, ATTN_SMEM);

    embed_kernel<<<MTOT * DD / 256, 256>>>(ctx, W_e, b_e, cls, px);

    for (int l = 0; l < LL; l++) {
        ln_kernel<<<MTOT / 8, 256>>>(px, ln1_w + l * DD, ln1_b + l * DD, ph);
        gemm_wmma<0,0><<<dim3(MTOT / BM, 960 / BN), 256, GSM_BYTES>>>(
            ph, W_in + (size_t)l * 3 * DD * DD, b_in + l * 3 * DD, nullptr,
            pbig, DD, 3 * DD);
        attn_kernel<<<BB, 256, ATTN_SMEM>>>(pbig, ph);
        gemm_wmma<0,1><<<dim3(MTOT / BM, DD / BN), 256, GSM_BYTES>>>(
            ph, W_out + (size_t)l * DD * DD, b_out + l * DD, px,
            px, DD, DD);
        ln_kernel<<<MTOT / 8, 256>>>(px, ln2_w + l * DD, ln2_b + l * DD, ph);
        gemm_wmma<1,0><<<dim3(MTOT / BM, FFN / BN), 256, GSM_BYTES>>>(
            ph, W1 + (size_t)l * FFN * DD, b1 + l * FFN, nullptr,
            pbig, DD, FFN);
        gemm_wmma<0,1><<<dim3(MTOT / BM, DD / BN), 256, GSM_BYTES>>>(
            pbig, W2 + (size_t)l * DD * FFN, b2 + l * DD, px,
            px, FFN, DD);
    }

    head_kernel<<<BB, 320>>>(px, hln_w, hln_b, Wh1, bh1, Wh2, bh2);
    cheb_kernel<<<BB * 2, 256>>>(k_norm, (float*)d_out);
}

// round 4
// speedup vs baseline: 2.8111x; 1.0159x over previous
#include <cuda_runtime.h>
#include <math.h>
#include <stdint.h>
#include <mma.h>

using namespace nvcuda;

#define BB 1024
#define TT 512
#define CTXN 23
#define DD 320
#define LL 5
#define HH 8
#define FFN 1280
#define NM 49      // NMODES+1
#define SS 24      // CLS + 23 tokens
#define DHD 40
#define MTOT (BB * SS)   // 24576

// ------------------------------------------------------------------
// Global scratch
// ------------------------------------------------------------------
__device__ float g_x[MTOT * DD];      // residual stream
__device__ float g_h[MTOT * DD];      // LN output / attn output (tf32-rounded)
__device__ float g_big[MTOT * FFN];   // qkv (960 cols) / ffn hidden
__device__ float g_c[BB * NM];        // chebyshev coefficients
// tf32-rounded weight copies: W_in | W_out | W1 | W2
#define WR_WIN  0
#define WR_WOUT 1536000
#define WR_W1   2048000
#define WR_W2   4096000
#define WR_TOT  6144000
__device__ float g_wr[WR_TOT];

__device__ __forceinline__ uint32_t smem_u32(const void* p) {
    uint32_t a;
    asm("{ .reg .u64 t; cvta.to.shared.u64 t, %1; cvt.u32.u64 %0, t; }"
        : "=r"(a) : "l"(p));
    return a;
}
__device__ __forceinline__ void cp_async16(uint32_t s, const void* g) {
    asm volatile("cp.async.cg.shared.global [%0], [%1], 16;" :: "r"(s), "l"(g));
}
#define CP_COMMIT() asm volatile("cp.async.commit_group;" ::: "memory")
#define CP_WAIT(n)  asm volatile("cp.async.wait_group %0;" :: "n"(n) : "memory")
__device__ __forceinline__ float to_tf32(float x) {
    float r; asm("cvt.rna.tf32.f32 %0, %1;" : "=f"(r) : "f"(x)); return r;
}

// ------------------------------------------------------------------
// wmma tf32 GEMM:  C[m,n] = act( A[m,:].B[n,:] + bias[n] ) (+ R[m,n])
// A: [M, K] row-major (pre-rounded tf32). B: [N, K] row-major (pre-rounded).
// 128 x 64 x 32 tiles, 4-stage cp.async pipeline, no in-loop cvt.
// ------------------------------------------------------------------
#define BM 128
#define BN 64
#define BK 32
#define STAGES 4
#define ASTR 36
#define BSTR 36
#define CSTR 68
#define A_BUF (BM * ASTR)
#define B_BUF (BN * BSTR)
#define STAGE_F (A_BUF + B_BUF)                 // 6912 floats
#define GSM_BYTES (STAGES * STAGE_F * 4)        // 110592 B

template<int ACT, int RES>
__global__ void __launch_bounds__(256)
gemm_wmma(const float* __restrict__ A, const float* __restrict__ B,
          const float* __restrict__ bias, const float* __restrict__ R,
          float* __restrict__ C, int K, int N)
{
    extern __shared__ float sm[];
    const int tid = threadIdx.x;
    const int wid = tid >> 5;
    const int wm = wid & 3;          // warp row 0..3  (32 rows each)
    const int wn = wid >> 2;         // warp col 0..1  (32 cols each)
    const int mbase = blockIdx.x * BM;
    const int nbase = blockIdx.y * BN;
    const int KT = K / BK;

    wmma::fragment<wmma::accumulator, 16, 16, 8, float> acc[2][2];
    #pragma unroll
    for (int i = 0; i < 2; i++)
        #pragma unroll
        for (int j = 0; j < 2; j++) wmma::fill_fragment(acc[i][j], 0.0f);

    uint32_t sbase = smem_u32(sm);
    const int arow = tid >> 3, ac4 = tid & 7;   // A: 4 rounds of 32 rows
    const int brow = tid >> 3, bc4 = tid & 7;   // B: 2 rounds of 32 rows

    auto load_tile = [&](int kt, int buf) {
        const float* Ag = A + (size_t)mbase * K + kt * BK;
        const float* Bg = B + (size_t)nbase * K + kt * BK;
        uint32_t sA = sbase + (uint32_t)(buf * STAGE_F) * 4;
        uint32_t sB = sA + (uint32_t)A_BUF * 4;
        #pragma unroll
        for (int t = 0; t < 4; t++) {
            int row = t * 32 + arow;
            cp_async16(sA + (uint32_t)(row * ASTR + ac4 * 4) * 4,
                       Ag + (size_t)row * K + ac4 * 4);
        }
        #pragma unroll
        for (int t = 0; t < 2; t++) {
            int row = t * 32 + brow;
            cp_async16(sB + (uint32_t)(row * BSTR + bc4 * 4) * 4,
                       Bg + (size_t)row * K + bc4 * 4);
        }
        CP_COMMIT();
    };

    load_tile(0, 0);
    load_tile(1, 1);
    load_tile(2, 2);

    for (int kt = 0; kt < KT; kt++) {
        CP_WAIT(2);
        __syncthreads();
        if (kt + 3 < KT) load_tile(kt + 3, (kt + 3) & (STAGES - 1));
        else             CP_COMMIT();

        const float* Ab = sm + (kt & (STAGES - 1)) * STAGE_F + wm * 32 * ASTR;
        const float* Bb = sm + (kt & (STAGES - 1)) * STAGE_F + A_BUF + wn * 32 * BSTR;
        #pragma unroll
        for (int k0 = 0; k0 < BK; k0 += 8) {
            wmma::fragment<wmma::matrix_a, 16, 16, 8, wmma::precision::tf32,
                           wmma::row_major> af[2];
            wmma::fragment<wmma::matrix_b, 16, 16, 8, wmma::precision::tf32,
                           wmma::col_major> bf[2];
            #pragma unroll
            for (int i = 0; i < 2; i++)
                wmma::load_matrix_sync(af[i], Ab + i * 16 * ASTR + k0, ASTR);
            #pragma unroll
            for (int j = 0; j < 2; j++)
                wmma::load_matrix_sync(bf[j], Bb + j * 16 * BSTR + k0, BSTR);
            #pragma unroll
            for (int i = 0; i < 2; i++)
                #pragma unroll
                for (int j = 0; j < 2; j++)
                    wmma::mma_sync(acc[i][j], af[i], bf[j], acc[i][j]);
        }
    }
    __syncthreads();

    // epilogue: stage in SMEM, fuse bias/act/residual
    float* Cs = sm;   // 128 x CSTR
    #pragma unroll
    for (int i = 0; i < 2; i++)
        #pragma unroll
        for (int j = 0; j < 2; j++)
            wmma::store_matrix_sync(Cs + (wm * 32 + i * 16) * CSTR + wn * 32 + j * 16,
                                    acc[i][j], CSTR, wmma::mem_row_major);
    __syncthreads();

    #pragma unroll 4
    for (int idx = tid; idx < BM * BN; idx += 256) {
        int r = idx >> 6, c = idx & 63;
        float v = Cs[r * CSTR + c] + bias[nbase + c];
        if (ACT) {
            v = 0.5f * v * (1.f + erff(v * 0.70710678118654752f));
            v = to_tf32(v);        // feeds next GEMM's A
        }
        size_t gi = (size_t)(mbase + r) * N + nbase + c;
        if (RES) v += R[gi];
        C[gi] = v;
    }
}

// ------------------------------------------------------------------
// Weight rounding (once per replay)
// ------------------------------------------------------------------
__global__ void __launch_bounds__(256)
round_copy(const float* __restrict__ s, float* __restrict__ d, int n)
{
    int i = blockIdx.x * 256 + threadIdx.x;
    if (i < n) d[i] = to_tf32(s[i]);
}

// ------------------------------------------------------------------
// Elementwise / small kernels
// ------------------------------------------------------------------
__global__ void __launch_bounds__(256)
embed_kernel(const float* __restrict__ ctx, const float* __restrict__ W_e,
             const float* __restrict__ b_e, const float* __restrict__ cls,
             float* __restrict__ X)
{
    int i = blockIdx.x * 256 + threadIdx.x;
    int d = i % DD;
    int s = (i / DD) % SS;
    int b = i / (DD * SS);
    float v;
    if (s == 0) v = cls[d];
    else        v = ctx[b * CTXN + (s - 1)] * W_e[d] + b_e[d];
    X[i] = v;
}

// one warp per row of 320; output tf32-rounded (feeds GEMM A)
__global__ void __launch_bounds__(256)
ln_kernel(const float* __restrict__ X, const float* __restrict__ w,
          const float* __restrict__ b, float* __restrict__ O)
{
    int row = blockIdx.x * 8 + (threadIdx.x >> 5);
    int lane = threadIdx.x & 31;
    const float* xr = X + (size_t)row * DD;
    float sum = 0.f, sq = 0.f;
    #pragma unroll
    for (int k = lane; k < DD; k += 32) { float v = xr[k]; sum += v; sq += v * v; }
    #pragma unroll
    for (int o = 16; o > 0; o >>= 1) {
        sum += __shfl_xor_sync(0xffffffffu, sum, o);
        sq  += __shfl_xor_sync(0xffffffffu, sq, o);
    }
    float mean = sum * (1.f / DD);
    float var  = sq * (1.f / DD) - mean * mean;
    float inv  = rsqrtf(var + 1e-5f);
    float* orow = O + (size_t)row * DD;
    #pragma unroll
    for (int k = lane; k < DD; k += 32)
        orow[k] = to_tf32((xr[k] - mean) * inv * w[k] + b[k]);
}

// attention for one batch element; output tf32-rounded (feeds W_out GEMM A)
#define QST 964
#define ATTN_SMEM ((SS * QST + HH * SS * SS) * 4)
__global__ void __launch_bounds__(256)
attn_kernel(const float* __restrict__ qkv, float* __restrict__ o)
{
    extern __shared__ float smf[];
    float* t  = smf;             // [24][QST]: q 0-319, k 320-639, v 640-959
    float* sc = smf + SS * QST;  // [8*24*24]
    const int b = blockIdx.x, tid = threadIdx.x;

    const float4* src = (const float4*)(qkv + (size_t)b * SS * 960);
    for (int i = tid; i < SS * 240; i += 256) {
        int r = i / 240, c = i - r * 240;
        ((float4*)(t + r * QST))[c] = src[r * 240 + c];
    }
    __syncthreads();

    for (int idx = tid; idx < HH * SS * SS; idx += 256) {
        int h = idx / (SS * SS);
        int rem = idx - h * (SS * SS);
        int i = rem / SS, j = rem - i * SS;
        const float* q = t + i * QST + h * DHD;
        const float* k = t + j * QST + DD + h * DHD;
        float s = 0.f;
        #pragma unroll
        for (int d = 0; d < DHD; d += 4)
            s += q[d] * k[d] + q[d+1] * k[d+1] + q[d+2] * k[d+2] + q[d+3] * k[d+3];
        sc[idx] = s * 0.15811388300841897f;
    }
    __syncthreads();

    if (tid < HH * SS) {
        float* row = sc + tid * SS;
        float mx = row[0];
        #pragma unroll
        for (int j = 1; j < SS; j++) mx = fmaxf(mx, row[j]);
        float sum = 0.f;
        #pragma unroll
        for (int j = 0; j < SS; j++) { float e = expf(row[j] - mx); row[j] = e; sum += e; }
        float inv = 1.f / sum;
        #pragma unroll
        for (int j = 0; j < SS; j++) row[j] *= inv;
    }
    __syncthreads();

    for (int idx = tid; idx < SS * DD; idx += 256) {
        int i = idx / DD, d = idx - i * DD;
        int h = d / DHD;
        const float* a = sc + (h * SS + i) * SS;
        float acc = 0.f;
        #pragma unroll
        for (int j = 0; j < SS; j++) acc += a[j] * t[j * QST + 2 * DD + d];
        o[(size_t)(b * SS + i) * DD + d] = to_tf32(acc);
    }
}

// CLS head: LN -> gelu(Wh1) -> Wh2 -> g_c
__global__ void __launch_bounds__(320)
head_kernel(const float* __restrict__ X,
            const float* __restrict__ hln_w, const float* __restrict__ hln_b,
            const float* __restrict__ Wh1,   const float* __restrict__ bh1,
            const float* __restrict__ Wh2,   const float* __restrict__ bh2)
{
    __shared__ float hbuf[DD], scr[DD], wsum[10], wsq[10], red[2];
    const int b = blockIdx.x, tid = threadIdx.x;
    const float* xr = X + (size_t)b * SS * DD;

    float v = xr[tid];
    float sum = v, sq = v * v;
    #pragma unroll
    for (int o = 16; o > 0; o >>= 1) {
        sum += __shfl_xor_sync(0xffffffffu, sum, o);
        sq  += __shfl_xor_sync(0xffffffffu, sq, o);
    }
    int wid = tid >> 5, lane = tid & 31;
    if (lane == 0) { wsum[wid] = sum; wsq[wid] = sq; }
    __syncthreads();
    if (tid == 0) {
        float s = 0.f, q = 0.f;
        #pragma unroll
        for (int w = 0; w < 10; w++) { s += wsum[w]; q += wsq[w]; }
        float mean = s * (1.f / DD);
        float var  = q * (1.f / DD) - mean * mean;
        red[0] = mean; red[1] = rsqrtf(var + 1e-5f);
    }
    __syncthreads();
    hbuf[tid] = (v - red[0]) * red[1] * hln_w[tid] + hln_b[tid];
    __syncthreads();

    {
        const float4* Wr = (const float4*)(Wh1 + (size_t)tid * DD);
        float acc = 0.f;
        #pragma unroll 4
        for (int k4 = 0; k4 < DD / 4; k4++) {
            float4 w = Wr[k4];
            float4 a = ((const float4*)hbuf)[k4];
            acc += a.x * w.x + a.y * w.y + a.z * w.z + a.w * w.w;
        }
        acc += bh1[tid];
        scr[tid] = 0.5f * acc * (1.f + erff(acc * 0.70710678118654752f));
    }
    __syncthreads();

    if (tid < NM) {
        const float4* Wr = (const float4*)(Wh2 + (size_t)tid * DD);
        float acc = 0.f;
        #pragma unroll 4
        for (int k4 = 0; k4 < DD / 4; k4++) {
            float4 w = Wr[k4];
            float4 a = ((const float4*)scr)[k4];
            acc += a.x * w.x + a.y * w.y + a.z * w.z + a.w * w.w;
        }
        g_c[b * NM + tid] = acc + bh2[tid];
    }
}

__global__ void __launch_bounds__(256)
cheb_kernel(const float* __restrict__ k_norm, float* __restrict__ out)
{
    __shared__ float c[NM];
    const int b = blockIdx.x >> 1;
    const int t = ((blockIdx.x & 1) << 8) + threadIdx.x;
    if (threadIdx.x < NM) c[threadIdx.x] = g_c[b * NM + threadIdx.x];
    __syncthreads();
    float xx = k_norm[b * TT + t];
    float tp = 1.f, tc = xx;
    float acc = c[0] + c[1] * xx;
    float x2 = 2.f * xx;
    #pragma unroll
    for (int n = 2; n < NM; n++) {
        float tn = x2 * tc - tp;
        acc += c[n] * tn;
        tp = tc; tc = tn;
    }
    out[b * TT + t] = 1.f / (1.f + expf(-acc));
}

// ------------------------------------------------------------------
// Host
// ------------------------------------------------------------------
extern "C" void kernel_launch(void* const* d_in, const int* in_sizes, int n_in,
                              void* d_out, int out_size)
{
    const float* k_norm = (const float*)d_in[0];
    const float* ctx    = (const float*)d_in[1];
    const float* W_e    = (const float*)d_in[2];
    const float* b_e    = (const float*)d_in[3];
    const float* cls    = (const float*)d_in[4];
    const float* ln1_w  = (const float*)d_in[5];
    const float* ln1_b  = (const float*)d_in[6];
    const float* W_in   = (const float*)d_in[7];
    const float* b_in   = (const float*)d_in[8];
    const float* W_out  = (const float*)d_in[9];
    const float* b_out  = (const float*)d_in[10];
    const float* ln2_w  = (const float*)d_in[11];
    const float* ln2_b  = (const float*)d_in[12];
    const float* W1     = (const float*)d_in[13];
    const float* b1     = (const float*)d_in[14];
    const float* W2     = (const float*)d_in[15];
    const float* b2     = (const float*)d_in[16];
    const float* hln_w  = (const float*)d_in[17];
    const float* hln_b  = (const float*)d_in[18];
    const float* Wh1    = (const float*)d_in[19];
    const float* bh1    = (const float*)d_in[20];
    const float* Wh2    = (const float*)d_in[21];
    const float* bh2    = (const float*)d_in[22];

    float *px, *ph, *pbig, *pwr;
    cudaGetSymbolAddress((void**)&px,   g_x);
    cudaGetSymbolAddress((void**)&ph,   g_h);
    cudaGetSymbolAddress((void**)&pbig, g_big);
    cudaGetSymbolAddress((void**)&pwr,  g_wr);

    cudaFuncSetAttribute(gemm_wmma<0,0>, cudaFuncAttributeMaxDynamicSharedMemorySize, GSM_BYTES);
    cudaFuncSetAttribute(gemm_wmma<0,1>, cudaFuncAttributeMaxDynamicSharedMemorySize, GSM_BYTES);
    cudaFuncSetAttribute(gemm_wmma<1,0>, cudaFuncAttributeMaxDynamicSharedMemorySize, GSM_BYTES);
    cudaFuncSetAttribute(attn_kernel,    cudaFuncAttributeMaxDynamicSharedMemorySize, ATTN_SMEM);

    // weight rounding (tf32), once per replay
    round_copy<<<(LL*3*DD*DD + 255)/256, 256>>>(W_in,  pwr + WR_WIN,  LL*3*DD*DD);
    round_copy<<<(LL*DD*DD   + 255)/256, 256>>>(W_out, pwr + WR_WOUT, LL*DD*DD);
    round_copy<<<(LL*FFN*DD  + 255)/256, 256>>>(W1,    pwr + WR_W1,   LL*FFN*DD);
    round_copy<<<(LL*DD*FFN  + 255)/256, 256>>>(W2,    pwr + WR_W2,   LL*DD*FFN);

    embed_kernel<<<MTOT * DD / 256, 256>>>(ctx, W_e, b_e, cls, px);

    for (int l = 0; l < LL; l++) {
        ln_kernel<<<MTOT / 8, 256>>>(px, ln1_w + l * DD, ln1_b + l * DD, ph);
        gemm_wmma<0,0><<<dim3(MTOT / BM, 960 / BN), 256, GSM_BYTES>>>(
            ph, pwr + WR_WIN + (size_t)l * 3 * DD * DD, b_in + l * 3 * DD, nullptr,
            pbig, DD, 3 * DD);
        attn_kernel<<<BB, 256, ATTN_SMEM>>>(pbig, ph);
        gemm_wmma<0,1><<<dim3(MTOT / BM, DD / BN), 256, GSM_BYTES>>>(
            ph, pwr + WR_WOUT + (size_t)l * DD * DD, b_out + l * DD, px,
            px, DD, DD);
        ln_kernel<<<MTOT / 8, 256>>>(px, ln2_w + l * DD, ln2_b + l * DD, ph);
        gemm_wmma<1,0><<<dim3(MTOT / BM, FFN / BN), 256, GSM_BYTES>>>(
            ph, pwr + WR_W1 + (size_t)l * FFN * DD, b1 + l * FFN, nullptr,
            pbig, DD, FFN);
        gemm_wmma<0,1><<<dim3(MTOT / BM, DD / BN), 256, GSM_BYTES>>>(
            pbig, pwr + WR_W2 + (size_t)l * DD * FFN, b2 + l * DD, px,
            px, FFN, DD);
    }

    head_kernel<<<BB, 320>>>(px, hln_w, hln_b, Wh1, bh1, Wh2, bh2);
    cheb_kernel<<<BB * 2, 256>>>(k_norm, (float*)d_out);
}

// round 5
// speedup vs baseline: 2.8912x; 1.0285x over previous
#include <cuda_runtime.h>
#include <math.h>
#include <stdint.h>
#include <mma.h>

using namespace nvcuda;

#define BB 1024
#define TT 512
#define CTXN 23
#define DD 320
#define LL 5
#define HH 8
#define FFN 1280
#define NM 49      // NMODES+1
#define SS 24      // CLS + 23 tokens
#define DHD 40
#define MTOT (BB * SS)   // 24576

// ------------------------------------------------------------------
// Global scratch
// ------------------------------------------------------------------
__device__ float g_x[MTOT * DD];      // residual stream
__device__ float g_h[MTOT * DD];      // LN output / attn output (tf32-rounded)
__device__ float g_big[MTOT * FFN];   // qkv (960 cols) / ffn hidden
__device__ float g_c[BB * NM];        // chebyshev coefficients
// tf32-rounded weight copies: W_in | W_out | W1 | W2
#define WR_WIN  0
#define WR_WOUT 1536000
#define WR_W1   2048000
#define WR_W2   4096000
#define WR_TOT  6144000
__device__ float g_wr[WR_TOT];

__device__ __forceinline__ uint32_t smem_u32(const void* p) {
    uint32_t a;
    asm("{ .reg .u64 t; cvta.to.shared.u64 t, %1; cvt.u32.u64 %0, t; }"
        : "=r"(a) : "l"(p));
    return a;
}
__device__ __forceinline__ void cp_async16(uint32_t s, const void* g) {
    asm volatile("cp.async.cg.shared.global [%0], [%1], 16;" :: "r"(s), "l"(g));
}
#define CP_COMMIT() asm volatile("cp.async.commit_group;" ::: "memory")
#define CP_WAIT(n)  asm volatile("cp.async.wait_group %0;" :: "n"(n) : "memory")
__device__ __forceinline__ float to_tf32(float x) {
    float r; asm("cvt.rna.tf32.f32 %0, %1;" : "=f"(r) : "f"(x)); return r;
}

// ------------------------------------------------------------------
// wmma tf32 GEMM:  C[m,n] = act( A[m,:].B[n,:] + bias[n] ) (+ R[m,n])
// A: [M, K] row-major (pre-rounded tf32). B: [N, K] row-major (pre-rounded).
// 256 x 64 x 32 block tile, 8 warps in 4x2 -> 64x32 warp tiles, 2 stages.
// ------------------------------------------------------------------
#define BM 256
#define BN 64
#define BK 32
#define STAGES 2
#define ASTR 36
#define BSTR 36
#define CSTR 68
#define A_BUF (BM * ASTR)                       // 9216 floats
#define B_BUF (BN * BSTR)                       // 2304 floats
#define STAGE_F (A_BUF + B_BUF)                 // 11520 floats
#define GSM_BYTES (STAGES * STAGE_F * 4)        // 92160 B

template<int ACT, int RES>
__global__ void __launch_bounds__(256, 2)
gemm_wmma(const float* __restrict__ A, const float* __restrict__ B,
          const float* __restrict__ bias, const float* __restrict__ R,
          float* __restrict__ C, int K, int N)
{
    extern __shared__ float sm[];
    const int tid = threadIdx.x;
    const int wid = tid >> 5;
    const int wm = wid >> 1;         // warp row 0..3  (64 rows each)
    const int wn = wid & 1;          // warp col 0..1  (32 cols each)
    const int mbase = blockIdx.x * BM;
    const int nbase = blockIdx.y * BN;
    const int KT = K / BK;

    wmma::fragment<wmma::accumulator, 16, 16, 8, float> acc[4][2];
    #pragma unroll
    for (int i = 0; i < 4; i++)
        #pragma unroll
        for (int j = 0; j < 2; j++) wmma::fill_fragment(acc[i][j], 0.0f);

    uint32_t sbase = smem_u32(sm);
    const int arow = tid >> 3, ac4 = tid & 7;   // A: 8 rounds of 32 rows
    const int brow = tid >> 3, bc4 = tid & 7;   // B: 2 rounds of 32 rows

    auto load_tile = [&](int kt, int buf) {
        const float* Ag = A + (size_t)mbase * K + kt * BK;
        const float* Bg = B + (size_t)nbase * K + kt * BK;
        uint32_t sA = sbase + (uint32_t)(buf * STAGE_F) * 4;
        uint32_t sB = sA + (uint32_t)A_BUF * 4;
        #pragma unroll
        for (int t = 0; t < 8; t++) {
            int row = t * 32 + arow;
            cp_async16(sA + (uint32_t)(row * ASTR + ac4 * 4) * 4,
                       Ag + (size_t)row * K + ac4 * 4);
        }
        #pragma unroll
        for (int t = 0; t < 2; t++) {
            int row = t * 32 + brow;
            cp_async16(sB + (uint32_t)(row * BSTR + bc4 * 4) * 4,
                       Bg + (size_t)row * K + bc4 * 4);
        }
        CP_COMMIT();
    };

    load_tile(0, 0);

    for (int kt = 0; kt < KT; kt++) {
        const int cur = kt & 1;
        if (kt + 1 < KT) { load_tile(kt + 1, 1 - cur); CP_WAIT(1); }
        else             { CP_WAIT(0); }
        __syncthreads();

        const float* Ab = sm + cur * STAGE_F + wm * 64 * ASTR;
        const float* Bb = sm + cur * STAGE_F + A_BUF + wn * 32 * BSTR;
        #pragma unroll
        for (int k0 = 0; k0 < BK; k0 += 8) {
            wmma::fragment<wmma::matrix_a, 16, 16, 8, wmma::precision::tf32,
                           wmma::row_major> af[4];
            wmma::fragment<wmma::matrix_b, 16, 16, 8, wmma::precision::tf32,
                           wmma::col_major> bf[2];
            #pragma unroll
            for (int j = 0; j < 2; j++)
                wmma::load_matrix_sync(bf[j], Bb + j * 16 * BSTR + k0, BSTR);
            #pragma unroll
            for (int i = 0; i < 4; i++) {
                wmma::load_matrix_sync(af[i], Ab + i * 16 * ASTR + k0, ASTR);
                #pragma unroll
                for (int j = 0; j < 2; j++)
                    wmma::mma_sync(acc[i][j], af[i], bf[j], acc[i][j]);
            }
        }
        __syncthreads();
    }

    // epilogue: stage in SMEM, fuse bias/act/residual
    float* Cs = sm;   // 256 x CSTR floats = 69632 B  (fits in 92160)
    #pragma unroll
    for (int i = 0; i < 4; i++)
        #pragma unroll
        for (int j = 0; j < 2; j++)
            wmma::store_matrix_sync(Cs + (wm * 64 + i * 16) * CSTR + wn * 32 + j * 16,
                                    acc[i][j], CSTR, wmma::mem_row_major);
    __syncthreads();

    #pragma unroll 8
    for (int idx = tid; idx < BM * BN; idx += 256) {
        int r = idx >> 6, c = idx & 63;
        float v = Cs[r * CSTR + c] + bias[nbase + c];
        if (ACT) {
            v = 0.5f * v * (1.f + erff(v * 0.70710678118654752f));
            v = to_tf32(v);        // feeds next GEMM's A
        }
        size_t gi = (size_t)(mbase + r) * N + nbase + c;
        if (RES) v += R[gi];
        C[gi] = v;
    }
}

// ------------------------------------------------------------------
// Weight rounding (once per replay)
// ------------------------------------------------------------------
__global__ void __launch_bounds__(256)
round_copy(const float* __restrict__ s, float* __restrict__ d, int n)
{
    int i = blockIdx.x * 256 + threadIdx.x;
    if (i < n) d[i] = to_tf32(s[i]);
}

// ------------------------------------------------------------------
// Elementwise / small kernels
// ------------------------------------------------------------------
__global__ void __launch_bounds__(256)
embed_kernel(const float* __restrict__ ctx, const float* __restrict__ W_e,
             const float* __restrict__ b_e, const float* __restrict__ cls,
             float* __restrict__ X)
{
    int i = blockIdx.x * 256 + threadIdx.x;
    int d = i % DD;
    int s = (i / DD) % SS;
    int b = i / (DD * SS);
    float v;
    if (s == 0) v = cls[d];
    else        v = ctx[b * CTXN + (s - 1)] * W_e[d] + b_e[d];
    X[i] = v;
}

// one warp per row of 320; output tf32-rounded (feeds GEMM A)
__global__ void __launch_bounds__(256)
ln_kernel(const float* __restrict__ X, const float* __restrict__ w,
          const float* __restrict__ b, float* __restrict__ O)
{
    int row = blockIdx.x * 8 + (threadIdx.x >> 5);
    int lane = threadIdx.x & 31;
    const float* xr = X + (size_t)row * DD;
    float sum = 0.f, sq = 0.f;
    #pragma unroll
    for (int k = lane; k < DD; k += 32) { float v = xr[k]; sum += v; sq += v * v; }
    #pragma unroll
    for (int o = 16; o > 0; o >>= 1) {
        sum += __shfl_xor_sync(0xffffffffu, sum, o);
        sq  += __shfl_xor_sync(0xffffffffu, sq, o);
    }
    float mean = sum * (1.f / DD);
    float var  = sq * (1.f / DD) - mean * mean;
    float inv  = rsqrtf(var + 1e-5f);
    float* orow = O + (size_t)row * DD;
    #pragma unroll
    for (int k = lane; k < DD; k += 32)
        orow[k] = to_tf32((xr[k] - mean) * inv * w[k] + b[k]);
}

// attention for one batch element; output tf32-rounded (feeds W_out GEMM A)
#define QST 964
#define ATTN_SMEM ((SS * QST + HH * SS * SS) * 4)
__global__ void __launch_bounds__(256)
attn_kernel(const float* __restrict__ qkv, float* __restrict__ o)
{
    extern __shared__ float smf[];
    float* t  = smf;             // [24][QST]: q 0-319, k 320-639, v 640-959
    float* sc = smf + SS * QST;  // [8*24*24]
    const int b = blockIdx.x, tid = threadIdx.x;

    const float4* src = (const float4*)(qkv + (size_t)b * SS * 960);
    for (int i = tid; i < SS * 240; i += 256) {
        int r = i / 240, c = i - r * 240;
        ((float4*)(t + r * QST))[c] = src[r * 240 + c];
    }
    __syncthreads();

    for (int idx = tid; idx < HH * SS * SS; idx += 256) {
        int h = idx / (SS * SS);
        int rem = idx - h * (SS * SS);
        int i = rem / SS, j = rem - i * SS;
        const float* q = t + i * QST + h * DHD;
        const float* k = t + j * QST + DD + h * DHD;
        float s = 0.f;
        #pragma unroll
        for (int d = 0; d < DHD; d += 4)
            s += q[d] * k[d] + q[d+1] * k[d+1] + q[d+2] * k[d+2] + q[d+3] * k[d+3];
        sc[idx] = s * 0.15811388300841897f;
    }
    __syncthreads();

    if (tid < HH * SS) {
        float* row = sc + tid * SS;
        float mx = row[0];
        #pragma unroll
        for (int j = 1; j < SS; j++) mx = fmaxf(mx, row[j]);
        float sum = 0.f;
        #pragma unroll
        for (int j = 0; j < SS; j++) { float e = expf(row[j] - mx); row[j] = e; sum += e; }
        float inv = 1.f / sum;
        #pragma unroll
        for (int j = 0; j < SS; j++) row[j] *= inv;
    }
    __syncthreads();

    for (int idx = tid; idx < SS * DD; idx += 256) {
        int i = idx / DD, d = idx - i * DD;
        int h = d / DHD;
        const float* a = sc + (h * SS + i) * SS;
        float acc = 0.f;
        #pragma unroll
        for (int j = 0; j < SS; j++) acc += a[j] * t[j * QST + 2 * DD + d];
        o[(size_t)(b * SS + i) * DD + d] = to_tf32(acc);
    }
}

// CLS head: LN -> gelu(Wh1) -> Wh2 -> g_c
__global__ void __launch_bounds__(320)
head_kernel(const float* __restrict__ X,
            const float* __restrict__ hln_w, const float* __restrict__ hln_b,
            const float* __restrict__ Wh1,   const float* __restrict__ bh1,
            const float* __restrict__ Wh2,   const float* __restrict__ bh2)
{
    __shared__ float hbuf[DD], scr[DD], wsum[10], wsq[10], red[2];
    const int b = blockIdx.x, tid = threadIdx.x;
    const float* xr = X + (size_t)b * SS * DD;

    float v = xr[tid];
    float sum = v, sq = v * v;
    #pragma unroll
    for (int o = 16; o > 0; o >>= 1) {
        sum += __shfl_xor_sync(0xffffffffu, sum, o);
        sq  += __shfl_xor_sync(0xffffffffu, sq, o);
    }
    int wid = tid >> 5, lane = tid & 31;
    if (lane == 0) { wsum[wid] = sum; wsq[wid] = sq; }
    __syncthreads();
    if (tid == 0) {
        float s = 0.f, q = 0.f;
        #pragma unroll
        for (int w = 0; w < 10; w++) { s += wsum[w]; q += wsq[w]; }
        float mean = s * (1.f / DD);
        float var  = q * (1.f / DD) - mean * mean;
        red[0] = mean; red[1] = rsqrtf(var + 1e-5f);
    }
    __syncthreads();
    hbuf[tid] = (v - red[0]) * red[1] * hln_w[tid] + hln_b[tid];
    __syncthreads();

    {
        const float4* Wr = (const float4*)(Wh1 + (size_t)tid * DD);
        float acc = 0.f;
        #pragma unroll 4
        for (int k4 = 0; k4 < DD / 4; k4++) {
            float4 w = Wr[k4];
            float4 a = ((const float4*)hbuf)[k4];
            acc += a.x * w.x + a.y * w.y + a.z * w.z + a.w * w.w;
        }
        acc += bh1[tid];
        scr[tid] = 0.5f * acc * (1.f + erff(acc * 0.70710678118654752f));
    }
    __syncthreads();

    if (tid < NM) {
        const float4* Wr = (const float4*)(Wh2 + (size_t)tid * DD);
        float acc = 0.f;
        #pragma unroll 4
        for (int k4 = 0; k4 < DD / 4; k4++) {
            float4 w = Wr[k4];
            float4 a = ((const float4*)scr)[k4];
            acc += a.x * w.x + a.y * w.y + a.z * w.z + a.w * w.w;
        }
        g_c[b * NM + tid] = acc + bh2[tid];
    }
}

__global__ void __launch_bounds__(256)
cheb_kernel(const float* __restrict__ k_norm, float* __restrict__ out)
{
    __shared__ float c[NM];
    const int b = blockIdx.x >> 1;
    const int t = ((blockIdx.x & 1) << 8) + threadIdx.x;
    if (threadIdx.x < NM) c[threadIdx.x] = g_c[b * NM + threadIdx.x];
    __syncthreads();
    float xx = k_norm[b * TT + t];
    float tp = 1.f, tc = xx;
    float acc = c[0] + c[1] * xx;
    float x2 = 2.f * xx;
    #pragma unroll
    for (int n = 2; n < NM; n++) {
        float tn = x2 * tc - tp;
        acc += c[n] * tn;
        tp = tc; tc = tn;
    }
    out[b * TT + t] = 1.f / (1.f + expf(-acc));
}

// ------------------------------------------------------------------
// Host
// ------------------------------------------------------------------
extern "C" void kernel_launch(void* const* d_in, const int* in_sizes, int n_in,
                              void* d_out, int out_size)
{
    const float* k_norm = (const float*)d_in[0];
    const float* ctx    = (const float*)d_in[1];
    const float* W_e    = (const float*)d_in[2];
    const float* b_e    = (const float*)d_in[3];
    const float* cls    = (const float*)d_in[4];
    const float* ln1_w  = (const float*)d_in[5];
    const float* ln1_b  = (const float*)d_in[6];
    const float* W_in   = (const float*)d_in[7];
    const float* b_in   = (const float*)d_in[8];
    const float* W_out  = (const float*)d_in[9];
    const float* b_out  = (const float*)d_in[10];
    const float* ln2_w  = (const float*)d_in[11];
    const float* ln2_b  = (const float*)d_in[12];
    const float* W1     = (const float*)d_in[13];
    const float* b1     = (const float*)d_in[14];
    const float* W2     = (const float*)d_in[15];
    const float* b2     = (const float*)d_in[16];
    const float* hln_w  = (const float*)d_in[17];
    const float* hln_b  = (const float*)d_in[18];
    const float* Wh1    = (const float*)d_in[19];
    const float* bh1    = (const float*)d_in[20];
    const float* Wh2    = (const float*)d_in[21];
    const float* bh2    = (const float*)d_in[22];

    float *px, *ph, *pbig, *pwr;
    cudaGetSymbolAddress((void**)&px,   g_x);
    cudaGetSymbolAddress((void**)&ph,   g_h);
    cudaGetSymbolAddress((void**)&pbig, g_big);
    cudaGetSymbolAddress((void**)&pwr,  g_wr);

    cudaFuncSetAttribute(gemm_wmma<0,0>, cudaFuncAttributeMaxDynamicSharedMemorySize, GSM_BYTES);
    cudaFuncSetAttribute(gemm_wmma<0,1>, cudaFuncAttributeMaxDynamicSharedMemorySize, GSM_BYTES);
    cudaFuncSetAttribute(gemm_wmma<1,0>, cudaFuncAttributeMaxDynamicSharedMemorySize, GSM_BYTES);
    cudaFuncSetAttribute(attn_kernel,    cudaFuncAttributeMaxDynamicSharedMemorySize, ATTN_SMEM);

    // weight rounding (tf32), once per replay
    round_copy<<<(LL*3*DD*DD + 255)/256, 256>>>(W_in,  pwr + WR_WIN,  LL*3*DD*DD);
    round_copy<<<(LL*DD*DD   + 255)/256, 256>>>(W_out, pwr + WR_WOUT, LL*DD*DD);
    round_copy<<<(LL*FFN*DD  + 255)/256, 256>>>(W1,    pwr + WR_W1,   LL*FFN*DD);
    round_copy<<<(LL*DD*FFN  + 255)/256, 256>>>(W2,    pwr + WR_W2,   LL*DD*FFN);

    embed_kernel<<<MTOT * DD / 256, 256>>>(ctx, W_e, b_e, cls, px);

    for (int l = 0; l < LL; l++) {
        ln_kernel<<<MTOT / 8, 256>>>(px, ln1_w + l * DD, ln1_b + l * DD, ph);
        gemm_wmma<0,0><<<dim3(MTOT / BM, 960 / BN), 256, GSM_BYTES>>>(
            ph, pwr + WR_WIN + (size_t)l * 3 * DD * DD, b_in + l * 3 * DD, nullptr,
            pbig, DD, 3 * DD);
        attn_kernel<<<BB, 256, ATTN_SMEM>>>(pbig, ph);
        gemm_wmma<0,1><<<dim3(MTOT / BM, DD / BN), 256, GSM_BYTES>>>(
            ph, pwr + WR_WOUT + (size_t)l * DD * DD, b_out + l * DD, px,
            px, DD, DD);
        ln_kernel<<<MTOT / 8, 256>>>(px, ln2_w + l * DD, ln2_b + l * DD, ph);
        gemm_wmma<1,0><<<dim3(MTOT / BM, FFN / BN), 256, GSM_BYTES>>>(
            ph, pwr + WR_W1 + (size_t)l * FFN * DD, b1 + l * FFN, nullptr,
            pbig, DD, FFN);
        gemm_wmma<0,1><<<dim3(MTOT / BM, DD / BN), 256, GSM_BYTES>>>(
            pbig, pwr + WR_W2 + (size_t)l * DD * FFN, b2 + l * DD, px,
            px, FFN, DD);
    }

    head_kernel<<<BB, 320>>>(px, hln_w, hln_b, Wh1, bh1, Wh2, bh2);
    cheb_kernel<<<BB * 2, 256>>>(k_norm, (float*)d_out);
}

// round 10
// speedup vs baseline: 7.6319x; 2.6397x over previous
#include <cuda_runtime.h>
#include <cuda_fp16.h>
#include <math.h>
#include <stdint.h>
#include <mma.h>

using namespace nvcuda;

#define BB 1024
#define TT 512
#define CTXN 23
#define DD 320
#define LL 5
#define HH 8
#define FFN 1280
#define NM 49      // NMODES+1
#define SS 24      // CLS + 23 tokens
#define DHD 40
#define MTOT (BB * SS)   // 24576

// ------------------------------------------------------------------
// Global scratch
// ------------------------------------------------------------------
__device__ float  g_x[MTOT * DD];      // residual stream (fp32)
__device__ __half g_hh[MTOT * DD];     // LN / attn outputs (fp16, GEMM A)
__device__ float  g_big[MTOT * 3*DD];  // qkv (fp32, attention input)
__device__ __half g_bh[MTOT * FFN];    // ffn hidden (fp16, GEMM A)
__device__ float  g_c[BB * NM];        // chebyshev coefficients
// fp16 weight copies: W_in | W_out | W1 | W2
#define WR_WIN  0
#define WR_WOUT 1536000
#define WR_W1   2048000
#define WR_W2   4096000
#define WR_TOT  6144000
__device__ __half g_wh[WR_TOT];

__device__ __forceinline__ uint32_t smem_u32(const void* p) {
    uint32_t a;
    asm("{ .reg .u64 t; cvta.to.shared.u64 t, %1; cvt.u32.u64 %0, t; }"
        : "=r"(a) : "l"(p));
    return a;
}
__device__ __forceinline__ void cp_async16(uint32_t s, const void* g) {
    asm volatile("cp.async.cg.shared.global [%0], [%1], 16;" :: "r"(s), "l"(g));
}
#define CP_COMMIT() asm volatile("cp.async.commit_group;" ::: "memory")
#define CP_WAIT(n)  asm volatile("cp.async.wait_group %0;" :: "n"(n) : "memory")

// ------------------------------------------------------------------
// wmma fp16 GEMM (fp32 accumulate):
//   C[m,n] = act( A[m,:].B[n,:] + bias[n] ) (+ R[m,n])
// A: [M, K] fp16 row-major.  B: [N, K] fp16 row-major.
// 256 x 64 x 64 block tile, 8 warps in 4x2 -> 64x32 warp tiles, 2 stages.
// ------------------------------------------------------------------
#define BM 256
#define BN 64
#define BK 64
#define ASTR 72                                  // halves (144 B rows)
#define BSTR 72
#define CSTR 68                                  // floats (epilogue staging)
#define A_BUF (BM * ASTR)                        // 18432 halves
#define B_BUF (BN * BSTR)                        //  4608 halves
#define STAGE_H (A_BUF + B_BUF)                  // 23040 halves = 46080 B
#define GSM_BYTES (2 * STAGE_H * 2)              // 92160 B (>= 256*68*4 epilogue)

template<int ACT, int RES, typename OutT>
__global__ void __launch_bounds__(256, 2)
gemm_h(const __half* __restrict__ A, const __half* __restrict__ B,
       const float* __restrict__ bias, const float* __restrict__ R,
       OutT* __restrict__ C, int K, int N)
{
    extern __shared__ __align__(16) char smraw[];
    __half* smh = (__half*)smraw;
    const int tid = threadIdx.x;
    const int wid = tid >> 5;
    const int wm = wid >> 1;         // warp row 0..3  (64 rows each)
    const int wn = wid & 1;          // warp col 0..1  (32 cols each)
    const int mbase = blockIdx.x * BM;
    const int nbase = blockIdx.y * BN;
    const int KT = K / BK;

    wmma::fragment<wmma::accumulator, 16, 16, 16, float> acc[4][2];
    #pragma unroll
    for (int i = 0; i < 4; i++)
        #pragma unroll
        for (int j = 0; j < 2; j++) wmma::fill_fragment(acc[i][j], 0.0f);

    uint32_t sbase = smem_u32(smraw);
    const int arow = tid >> 3, ac8 = tid & 7;   // A: 8 rounds of 32 rows, 8 chunks/row
    const int brow = tid >> 3, bc8 = tid & 7;   // B: 2 rounds of 32 rows

    auto load_tile = [&](int kt, int buf) {
        const __half* Ag = A + (size_t)mbase * K + kt * BK;
        const __half* Bg = B + (size_t)nbase * K + kt * BK;
        uint32_t sA = sbase + (uint32_t)(buf * STAGE_H) * 2;
        uint32_t sB = sA + (uint32_t)A_BUF * 2;
        #pragma unroll
        for (int t = 0; t < 8; t++) {
            int row = t * 32 + arow;
            cp_async16(sA + (uint32_t)(row * ASTR + ac8 * 8) * 2,
                       Ag + (size_t)row * K + ac8 * 8);
        }
        #pragma unroll
        for (int t = 0; t < 2; t++) {
            int row = t * 32 + brow;
            cp_async16(sB + (uint32_t)(row * BSTR + bc8 * 8) * 2,
                       Bg + (size_t)row * K + bc8 * 8);
        }
        CP_COMMIT();
    };

    load_tile(0, 0);

    for (int kt = 0; kt < KT; kt++) {
        const int cur = kt & 1;
        if (kt + 1 < KT) { load_tile(kt + 1, 1 - cur); CP_WAIT(1); }
        else             { CP_WAIT(0); }
        __syncthreads();

        const __half* Ab = smh + cur * STAGE_H + wm * 64 * ASTR;
        const __half* Bb = smh + cur * STAGE_H + A_BUF + wn * 32 * BSTR;
        #pragma unroll
        for (int k0 = 0; k0 < BK; k0 += 16) {
            wmma::fragment<wmma::matrix_a, 16, 16, 16, __half, wmma::row_major> af[4];
            wmma::fragment<wmma::matrix_b, 16, 16, 16, __half, wmma::col_major> bf[2];
            #pragma unroll
            for (int j = 0; j < 2; j++)
                wmma::load_matrix_sync(bf[j], Bb + j * 16 * BSTR + k0, BSTR);
            #pragma unroll
            for (int i = 0; i < 4; i++) {
                wmma::load_matrix_sync(af[i], Ab + i * 16 * ASTR + k0, ASTR);
                #pragma unroll
                for (int j = 0; j < 2; j++)
                    wmma::mma_sync(acc[i][j], af[i], bf[j], acc[i][j]);
            }
        }
        __syncthreads();
    }

    // epilogue: stage in SMEM (fp32), fuse bias/act/residual
    float* Cs = (float*)smraw;   // 256 x CSTR floats = 69632 B (fits)
    #pragma unroll
    for (int i = 0; i < 4; i++)
        #pragma unroll
        for (int j = 0; j < 2; j++)
            wmma::store_matrix_sync(Cs + (wm * 64 + i * 16) * CSTR + wn * 32 + j * 16,
                                    acc[i][j], CSTR, wmma::mem_row_major);
    __syncthreads();

    #pragma unroll 8
    for (int idx = tid; idx < BM * BN; idx += 256) {
        int r = idx >> 6, c = idx & 63;
        float v = Cs[r * CSTR + c] + bias[nbase + c];
        if (ACT) v = 0.5f * v * (1.f + erff(v * 0.70710678118654752f));
        size_t gi = (size_t)(mbase + r) * N + nbase + c;
        if (RES) v += R[gi];
        if (sizeof(OutT) == 2) C[gi] = (OutT)__float2half_rn(v);
        else                   C[gi] = (OutT)v;
    }
}

// ------------------------------------------------------------------
// Weight conversion fp32 -> fp16 (once per replay)
// ------------------------------------------------------------------
__global__ void __launch_bounds__(256)
conv_h(const float* __restrict__ s, __half* __restrict__ d, int n)
{
    int i = blockIdx.x * 256 + threadIdx.x;
    if (i < n) d[i] = __float2half_rn(s[i]);
}

// ------------------------------------------------------------------
// Elementwise / small kernels
// ------------------------------------------------------------------
__global__ void __launch_bounds__(256)
embed_kernel(const float* __restrict__ ctx, const float* __restrict__ W_e,
             const float* __restrict__ b_e, const float* __restrict__ cls,
             float* __restrict__ X)
{
    int i = blockIdx.x * 256 + threadIdx.x;
    int d = i % DD;
    int s = (i / DD) % SS;
    int b = i / (DD * SS);
    float v;
    if (s == 0) v = cls[d];
    else        v = ctx[b * CTXN + (s - 1)] * W_e[d] + b_e[d];
    X[i] = v;
}

// one warp per row of 320; output fp16 (feeds GEMM A)
__global__ void __launch_bounds__(256)
ln_kernel(const float* __restrict__ X, const float* __restrict__ w,
          const float* __restrict__ b, __half* __restrict__ O)
{
    int row = blockIdx.x * 8 + (threadIdx.x >> 5);
    int lane = threadIdx.x & 31;
    const float* xr = X + (size_t)row * DD;
    float sum = 0.f, sq = 0.f;
    #pragma unroll
    for (int k = lane; k < DD; k += 32) { float v = xr[k]; sum += v; sq += v * v; }
    #pragma unroll
    for (int o = 16; o > 0; o >>= 1) {
        sum += __shfl_xor_sync(0xffffffffu, sum, o);
        sq  += __shfl_xor_sync(0xffffffffu, sq, o);
    }
    float mean = sum * (1.f / DD);
    float var  = sq * (1.f / DD) - mean * mean;
    float inv  = rsqrtf(var + 1e-5f);
    __half* orow = O + (size_t)row * DD;
    #pragma unroll
    for (int k = lane; k < DD; k += 32)
        orow[k] = __float2half_rn((xr[k] - mean) * inv * w[k] + b[k]);
}

// attention for one batch element; fp32 in, fp16 out (feeds W_out GEMM A)
#define QST 964
#define ATTN_SMEM ((SS * QST + HH * SS * SS) * 4)
__global__ void __launch_bounds__(256)
attn_kernel(const float* __restrict__ qkv, __half* __restrict__ o)
{
    extern __shared__ float smf[];
    float* t  = smf;             // [24][QST]: q 0-319, k 320-639, v 640-959
    float* sc = smf + SS * QST;  // [8*24*24]
    const int b = blockIdx.x, tid = threadIdx.x;

    const float4* src = (const float4*)(qkv + (size_t)b * SS * 960);
    for (int i = tid; i < SS * 240; i += 256) {
        int r = i / 240, c = i - r * 240;
        ((float4*)(t + r * QST))[c] = src[r * 240 + c];
    }
    __syncthreads();

    for (int idx = tid; idx < HH * SS * SS; idx += 256) {
        int h = idx / (SS * SS);
        int rem = idx - h * (SS * SS);
        int i = rem / SS, j = rem - i * SS;
        const float* q = t + i * QST + h * DHD;
        const float* k = t + j * QST + DD + h * DHD;
        float s = 0.f;
        #pragma unroll
        for (int d = 0; d < DHD; d += 4)
            s += q[d] * k[d] + q[d+1] * k[d+1] + q[d+2] * k[d+2] + q[d+3] * k[d+3];
        sc[idx] = s * 0.15811388300841897f;
    }
    __syncthreads();

    if (tid < HH * SS) {
        float* row = sc + tid * SS;
        float mx = row[0];
        #pragma unroll
        for (int j = 1; j < SS; j++) mx = fmaxf(mx, row[j]);
        float sum = 0.f;
        #pragma unroll
        for (int j = 0; j < SS; j++) { float e = expf(row[j] - mx); row[j] = e; sum += e; }
        float inv = 1.f / sum;
        #pragma unroll
        for (int j = 0; j < SS; j++) row[j] *= inv;
    }
    __syncthreads();

    for (int idx = tid; idx < SS * DD; idx += 256) {
        int i = idx / DD, d = idx - i * DD;
        int h = d / DHD;
        const float* a = sc + (h * SS + i) * SS;
        float acc = 0.f;
        #pragma unroll
        for (int j = 0; j < SS; j++) acc += a[j] * t[j * QST + 2 * DD + d];
        o[(size_t)(b * SS + i) * DD + d] = __float2half_rn(acc);
    }
}

// CLS head: LN -> gelu(Wh1) -> Wh2 -> g_c   (all fp32)
__global__ void __launch_bounds__(320)
head_kernel(const float* __restrict__ X,
            const float* __restrict__ hln_w, const float* __restrict__ hln_b,
            const float* __restrict__ Wh1,   const float* __restrict__ bh1,
            const float* __restrict__ Wh2,   const float* __restrict__ bh2)
{
    __shared__ float hbuf[DD], scr[DD], wsum[10], wsq[10], red[2];
    const int b = blockIdx.x, tid = threadIdx.x;
    const float* xr = X + (size_t)b * SS * DD;

    float v = xr[tid];
    float sum = v, sq = v * v;
    #pragma unroll
    for (int o = 16; o > 0; o >>= 1) {
        sum += __shfl_xor_sync(0xffffffffu, sum, o);
        sq  += __shfl_xor_sync(0xffffffffu, sq, o);
    }
    int wid = tid >> 5, lane = tid & 31;
    if (lane == 0) { wsum[wid] = sum; wsq[wid] = sq; }
    __syncthreads();
    if (tid == 0) {
        float s = 0.f, q = 0.f;
        #pragma unroll
        for (int w = 0; w < 10; w++) { s += wsum[w]; q += wsq[w]; }
        float mean = s * (1.f / DD);
        float var  = q * (1.f / DD) - mean * mean;
        red[0] = mean; red[1] = rsqrtf(var + 1e-5f);
    }
    __syncthreads();
    hbuf[tid] = (v - red[0]) * red[1] * hln_w[tid] + hln_b[tid];
    __syncthreads();

    {
        const float4* Wr = (const float4*)(Wh1 + (size_t)tid * DD);
        float acc = 0.f;
        #pragma unroll 4
        for (int k4 = 0; k4 < DD / 4; k4++) {
            float4 w = Wr[k4];
            float4 a = ((const float4*)hbuf)[k4];
            acc += a.x * w.x + a.y * w.y + a.z * w.z + a.w * w.w;
        }
        acc += bh1[tid];
        scr[tid] = 0.5f * acc * (1.f + erff(acc * 0.70710678118654752f));
    }
    __syncthreads();

    if (tid < NM) {
        const float4* Wr = (const float4*)(Wh2 + (size_t)tid * DD);
        float acc = 0.f;
        #pragma unroll 4
        for (int k4 = 0; k4 < DD / 4; k4++) {
            float4 w = Wr[k4];
            float4 a = ((const float4*)scr)[k4];
            acc += a.x * w.x + a.y * w.y + a.z * w.z + a.w * w.w;
        }
        g_c[b * NM + tid] = acc + bh2[tid];
    }
}

__global__ void __launch_bounds__(256)
cheb_kernel(const float* __restrict__ k_norm, float* __restrict__ out)
{
    __shared__ float c[NM];
    const int b = blockIdx.x >> 1;
    const int t = ((blockIdx.x & 1) << 8) + threadIdx.x;
    if (threadIdx.x < NM) c[threadIdx.x] = g_c[b * NM + threadIdx.x];
    __syncthreads();
    float xx = k_norm[b * TT + t];
    float tp = 1.f, tc = xx;
    float acc = c[0] + c[1] * xx;
    float x2 = 2.f * xx;
    #pragma unroll
    for (int n = 2; n < NM; n++) {
        float tn = x2 * tc - tp;
        acc += c[n] * tn;
        tp = tc; tc = tn;
    }
    out[b * TT + t] = 1.f / (1.f + expf(-acc));
}

// ------------------------------------------------------------------
// Host
// ------------------------------------------------------------------
extern "C" void kernel_launch(void* const* d_in, const int* in_sizes, int n_in,
                              void* d_out, int out_size)
{
    const float* k_norm = (const float*)d_in[0];
    const float* ctx    = (const float*)d_in[1];
    const float* W_e    = (const float*)d_in[2];
    const float* b_e    = (const float*)d_in[3];
    const float* cls    = (const float*)d_in[4];
    const float* ln1_w  = (const float*)d_in[5];
    const float* ln1_b  = (const float*)d_in[6];
    const float* W_in   = (const float*)d_in[7];
    const float* b_in   = (const float*)d_in[8];
    const float* W_out  = (const float*)d_in[9];
    const float* b_out  = (const float*)d_in[10];
    const float* ln2_w  = (const float*)d_in[11];
    const float* ln2_b  = (const float*)d_in[12];
    const float* W1     = (const float*)d_in[13];
    const float* b1     = (const float*)d_in[14];
    const float* W2     = (const float*)d_in[15];
    const float* b2     = (const float*)d_in[16];
    const float* hln_w  = (const float*)d_in[17];
    const float* hln_b  = (const float*)d_in[18];
    const float* Wh1    = (const float*)d_in[19];
    const float* bh1    = (const float*)d_in[20];
    const float* Wh2    = (const float*)d_in[21];
    const float* bh2    = (const float*)d_in[22];

    float *px, *pbig;
    __half *phh, *pbh, *pwh;
    cudaGetSymbolAddress((void**)&px,   g_x);
    cudaGetSymbolAddress((void**)&phh,  g_hh);
    cudaGetSymbolAddress((void**)&pbig, g_big);
    cudaGetSymbolAddress((void**)&pbh,  g_bh);
    cudaGetSymbolAddress((void**)&pwh,  g_wh);

    cudaFuncSetAttribute((void*)gemm_h<0,0,float>,  cudaFuncAttributeMaxDynamicSharedMemorySize, GSM_BYTES);
    cudaFuncSetAttribute((void*)gemm_h<0,1,float>,  cudaFuncAttributeMaxDynamicSharedMemorySize, GSM_BYTES);
    cudaFuncSetAttribute((void*)gemm_h<1,0,__half>, cudaFuncAttributeMaxDynamicSharedMemorySize, GSM_BYTES);
    cudaFuncSetAttribute((void*)attn_kernel,        cudaFuncAttributeMaxDynamicSharedMemorySize, ATTN_SMEM);

    // weight conversion (fp16), once per replay
    conv_h<<<(LL*3*DD*DD + 255)/256, 256>>>(W_in,  pwh + WR_WIN,  LL*3*DD*DD);
    conv_h<<<(LL*DD*DD   + 255)/256, 256>>>(W_out, pwh + WR_WOUT, LL*DD*DD);
    conv_h<<<(LL*FFN*DD  + 255)/256, 256>>>(W1,    pwh + WR_W1,   LL*FFN*DD);
    conv_h<<<(LL*DD*FFN  + 255)/256, 256>>>(W2,    pwh + WR_W2,   LL*DD*FFN);

    embed_kernel<<<MTOT * DD / 256, 256>>>(ctx, W_e, b_e, cls, px);

    for (int l = 0; l < LL; l++) {
        ln_kernel<<<MTOT / 8, 256>>>(px, ln1_w + l * DD, ln1_b + l * DD, phh);
        gemm_h<0,0,float><<<dim3(MTOT / BM, 960 / BN), 256, GSM_BYTES>>>(
            phh, pwh + WR_WIN + (size_t)l * 3 * DD * DD, b_in + l * 3 * DD, nullptr,
            pbig, DD, 3 * DD);
        attn_kernel<<<BB, 256, ATTN_SMEM>>>(pbig, phh);
        gemm_h<0,1,float><<<dim3(MTOT / BM, DD / BN), 256, GSM_BYTES>>>(
            phh, pwh + WR_WOUT + (size_t)l * DD * DD, b_out + l * DD, px,
            px, DD, DD);
        ln_kernel<<<MTOT / 8, 256>>>(px, ln2_w + l * DD, ln2_b + l * DD, phh);
        gemm_h<1,0,__half><<<dim3(MTOT / BM, FFN / BN), 256, GSM_BYTES>>>(
            phh, pwh + WR_W1 + (size_t)l * FFN * DD, b1 + l * FFN, nullptr,
            pbh, DD, FFN);
        gemm_h<0,1,float><<<dim3(MTOT / BM, DD / BN), 256, GSM_BYTES>>>(
            pbh, pwh + WR_W2 + (size_t)l * DD * FFN, b2 + l * DD, px,
            px, FFN, DD);
    }

    head_kernel<<<BB, 320>>>(px, hln_w, hln_b, Wh1, bh1, Wh2, bh2);
    cheb_kernel<<<BB * 2, 256>>>(k_norm, (float*)d_out);
}

// round 13
// speedup vs baseline: 7.9197x; 1.0377x over previous
#include <cuda_runtime.h>
#include <cuda_fp16.h>
#include <math.h>
#include <stdint.h>
#include <mma.h>

using namespace nvcuda;

#define BB 1024
#define TT 512
#define CTXN 23
#define DD 320
#define LL 5
#define HH 8
#define FFN 1280
#define NM 49      // NMODES+1
#define SS 24      // CLS + 23 tokens
#define DHD 40
#define MTOT (BB * SS)   // 24576

// ------------------------------------------------------------------
// Global scratch
// ------------------------------------------------------------------
__device__ float  g_x[MTOT * DD];      // residual stream (fp32)
__device__ __half g_hh[MTOT * DD];     // LN / attn outputs (fp16, GEMM A)
__device__ __half g_qkv[MTOT * 3*DD];  // qkv (fp16)
__device__ __half g_bh[MTOT * FFN];    // ffn hidden (fp16, GEMM A)
__device__ float  g_c[BB * NM];        // chebyshev coefficients
// fp16 weight copies: W_in | W_out | W1 | W2
#define WR_WIN  0
#define WR_WOUT 1536000
#define WR_W1   2048000
#define WR_W2   4096000
#define WR_TOT  6144000
__device__ __half g_wh[WR_TOT];

__device__ __forceinline__ uint32_t smem_u32(const void* p) {
    uint32_t a;
    asm("{ .reg .u64 t; cvta.to.shared.u64 t, %1; cvt.u32.u64 %0, t; }"
        : "=r"(a) : "l"(p));
    return a;
}
__device__ __forceinline__ void cp_async16(uint32_t s, const void* g) {
    asm volatile("cp.async.cg.shared.global [%0], [%1], 16;" :: "r"(s), "l"(g));
}
#define CP_COMMIT() asm volatile("cp.async.commit_group;" ::: "memory")
#define CP_WAIT(n)  asm volatile("cp.async.wait_group %0;" :: "n"(n) : "memory")

// ------------------------------------------------------------------
// wmma fp16 GEMM (fp32 accumulate):
//   C[m,n] = act( A[m,:].B[n,:] + bias[n] ) (+ R[m,n])
// 256 x 64 x 64 block tile, 8 warps in 4x2 -> 64x32 warp tiles, 2 stages.
// ------------------------------------------------------------------
#define BM 256
#define BN 64
#define BK 64
#define ASTR 72                                  // halves (144 B rows)
#define BSTR 72
#define CSTR 68                                  // floats (epilogue staging)
#define A_BUF (BM * ASTR)
#define B_BUF (BN * BSTR)
#define STAGE_H (A_BUF + B_BUF)                  // 23040 halves
#define GSM_BYTES (2 * STAGE_H * 2)              // 92160 B

template<int ACT, int RES, typename OutT>
__global__ void __launch_bounds__(256, 2)
gemm_h(const __half* __restrict__ A, const __half* __restrict__ B,
       const float* __restrict__ bias, const float* __restrict__ R,
       OutT* __restrict__ C, int K, int N)
{
    extern __shared__ __align__(16) char smraw[];
    __half* smh = (__half*)smraw;
    const int tid = threadIdx.x;
    const int wid = tid >> 5;
    const int wm = wid >> 1;
    const int wn = wid & 1;
    const int mbase = blockIdx.x * BM;
    const int nbase = blockIdx.y * BN;
    const int KT = K / BK;

    wmma::fragment<wmma::accumulator, 16, 16, 16, float> acc[4][2];
    #pragma unroll
    for (int i = 0; i < 4; i++)
        #pragma unroll
        for (int j = 0; j < 2; j++) wmma::fill_fragment(acc[i][j], 0.0f);

    uint32_t sbase = smem_u32(smraw);
    const int arow = tid >> 3, ac8 = tid & 7;
    const int brow = tid >> 3, bc8 = tid & 7;

    auto load_tile = [&](int kt, int buf) {
        const __half* Ag = A + (size_t)mbase * K + kt * BK;
        const __half* Bg = B + (size_t)nbase * K + kt * BK;
        uint32_t sA = sbase + (uint32_t)(buf * STAGE_H) * 2;
        uint32_t sB = sA + (uint32_t)A_BUF * 2;
        #pragma unroll
        for (int t = 0; t < 8; t++) {
            int row = t * 32 + arow;
            cp_async16(sA + (uint32_t)(row * ASTR + ac8 * 8) * 2,
                       Ag + (size_t)row * K + ac8 * 8);
        }
        #pragma unroll
        for (int t = 0; t < 2; t++) {
            int row = t * 32 + brow;
            cp_async16(sB + (uint32_t)(row * BSTR + bc8 * 8) * 2,
                       Bg + (size_t)row * K + bc8 * 8);
        }
        CP_COMMIT();
    };

    load_tile(0, 0);

    for (int kt = 0; kt < KT; kt++) {
        const int cur = kt & 1;
        if (kt + 1 < KT) { load_tile(kt + 1, 1 - cur); CP_WAIT(1); }
        else             { CP_WAIT(0); }
        __syncthreads();

        const __half* Ab = smh + cur * STAGE_H + wm * 64 * ASTR;
        const __half* Bb = smh + cur * STAGE_H + A_BUF + wn * 32 * BSTR;
        #pragma unroll
        for (int k0 = 0; k0 < BK; k0 += 16) {
            wmma::fragment<wmma::matrix_a, 16, 16, 16, __half, wmma::row_major> af[4];
            wmma::fragment<wmma::matrix_b, 16, 16, 16, __half, wmma::col_major> bf[2];
            #pragma unroll
            for (int j = 0; j < 2; j++)
                wmma::load_matrix_sync(bf[j], Bb + j * 16 * BSTR + k0, BSTR);
            #pragma unroll
            for (int i = 0; i < 4; i++) {
                wmma::load_matrix_sync(af[i], Ab + i * 16 * ASTR + k0, ASTR);
                #pragma unroll
                for (int j = 0; j < 2; j++)
                    wmma::mma_sync(acc[i][j], af[i], bf[j], acc[i][j]);
            }
        }
        __syncthreads();
    }

    // epilogue
    float* Cs = (float*)smraw;
    #pragma unroll
    for (int i = 0; i < 4; i++)
        #pragma unroll
        for (int j = 0; j < 2; j++)
            wmma::store_matrix_sync(Cs + (wm * 64 + i * 16) * CSTR + wn * 32 + j * 16,
                                    acc[i][j], CSTR, wmma::mem_row_major);
    __syncthreads();

    #pragma unroll 8
    for (int idx = tid; idx < BM * BN; idx += 256) {
        int r = idx >> 6, c = idx & 63;
        float v = Cs[r * CSTR + c] + bias[nbase + c];
        if (ACT) v = 0.5f * v * (1.f + erff(v * 0.70710678118654752f));
        size_t gi = (size_t)(mbase + r) * N + nbase + c;
        if (RES) v += R[gi];
        if (sizeof(OutT) == 2) C[gi] = (OutT)__float2half_rn(v);
        else                   C[gi] = (OutT)v;
    }
}

// ------------------------------------------------------------------
// Weight conversion fp32 -> fp16 (once per replay)
// ------------------------------------------------------------------
__global__ void __launch_bounds__(256)
conv_h(const float* __restrict__ s, __half* __restrict__ d, int n)
{
    int i = blockIdx.x * 256 + threadIdx.x;
    if (i < n) d[i] = __float2half_rn(s[i]);
}

// ------------------------------------------------------------------
// Elementwise / small kernels
// ------------------------------------------------------------------
__global__ void __launch_bounds__(256)
embed_kernel(const float* __restrict__ ctx, const float* __restrict__ W_e,
             const float* __restrict__ b_e, const float* __restrict__ cls,
             float* __restrict__ X)
{
    int i = blockIdx.x * 256 + threadIdx.x;
    int d = i % DD;
    int s = (i / DD) % SS;
    int b = i / (DD * SS);
    float v;
    if (s == 0) v = cls[d];
    else        v = ctx[b * CTXN + (s - 1)] * W_e[d] + b_e[d];
    X[i] = v;
}

// one warp per row of 320; output fp16 (feeds GEMM A)
__global__ void __launch_bounds__(256)
ln_kernel(const float* __restrict__ X, const float* __restrict__ w,
          const float* __restrict__ b, __half* __restrict__ O)
{
    int row = blockIdx.x * 8 + (threadIdx.x >> 5);
    int lane = threadIdx.x & 31;
    const float* xr = X + (size_t)row * DD;
    float sum = 0.f, sq = 0.f;
    #pragma unroll
    for (int k = lane; k < DD; k += 32) { float v = xr[k]; sum += v; sq += v * v; }
    #pragma unroll
    for (int o = 16; o > 0; o >>= 1) {
        sum += __shfl_xor_sync(0xffffffffu, sum, o);
        sq  += __shfl_xor_sync(0xffffffffu, sq, o);
    }
    float mean = sum * (1.f / DD);
    float var  = sq * (1.f / DD) - mean * mean;
    float inv  = rsqrtf(var + 1e-5f);
    __half* orow = O + (size_t)row * DD;
    #pragma unroll
    for (int k = lane; k < DD; k += 32)
        orow[k] = __float2half_rn((xr[k] - mean) * inv * w[k] + b[k]);
}

// attention for one batch element, fp16 qkv in smem, fp32 scores.
#define QSTH 968   // half stride per row (1936 B, 16B-aligned)
#define ATTN_SMEM (SS * QSTH * 2 + HH * SS * SS * 4)
__global__ void __launch_bounds__(256)
attn_kernel(const __half* __restrict__ qkv, __half* __restrict__ o)
{
    extern __shared__ __align__(16) char smc[];
    __half* t  = (__half*)smc;                       // [24][QSTH]
    float*  sc = (float*)(smc + SS * QSTH * 2);      // [8*24*24]
    const int b = blockIdx.x, tid = threadIdx.x;

    // load 24 x 960 halves = 24 x 120 float4
    const float4* src = (const float4*)(qkv + (size_t)b * SS * 960);
    for (int i = tid; i < SS * 120; i += 256) {
        int r = i / 120, c = i - r * 120;
        *(float4*)(t + r * QSTH + c * 8) = src[r * 120 + c];
    }
    __syncthreads();

    for (int idx = tid; idx < HH * SS * SS; idx += 256) {
        int h = idx / (SS * SS);
        int rem = idx - h * (SS * SS);
        int i = rem / SS, j = rem - i * SS;
        const __half2* q = (const __half2*)(t + i * QSTH + h * DHD);
        const __half2* k = (const __half2*)(t + j * QSTH + DD + h * DHD);
        float s = 0.f;
        #pragma unroll
        for (int d = 0; d < DHD / 2; d++) {
            float2 qf = __half22float2(q[d]);
            float2 kf = __half22float2(k[d]);
            s += qf.x * kf.x + qf.y * kf.y;
        }
        sc[idx] = s * 0.15811388300841897f;
    }
    __syncthreads();

    if (tid < HH * SS) {
        float* row = sc + tid * SS;
        float mx = row[0];
        #pragma unroll
        for (int j = 1; j < SS; j++) mx = fmaxf(mx, row[j]);
        float sum = 0.f;
        #pragma unroll
        for (int j = 0; j < SS; j++) { float e = expf(row[j] - mx); row[j] = e; sum += e; }
        float inv = 1.f / sum;
        #pragma unroll
        for (int j = 0; j < SS; j++) row[j] *= inv;
    }
    __syncthreads();

    for (int idx = tid; idx < SS * DD; idx += 256) {
        int i = idx / DD, d = idx - i * DD;
        int h = d / DHD;
        const float* a = sc + (h * SS + i) * SS;
        float acc = 0.f;
        #pragma unroll
        for (int j = 0; j < SS; j++)
            acc += a[j] * __half2float(t[j * QSTH + 2 * DD + d]);
        o[(size_t)(b * SS + i) * DD + d] = __float2half_rn(acc);
    }
}

// CLS head: LN -> gelu(Wh1) -> Wh2 -> g_c   (all fp32)
__global__ void __launch_bounds__(320)
head_kernel(const float* __restrict__ X,
            const float* __restrict__ hln_w, const float* __restrict__ hln_b,
            const float* __restrict__ Wh1,   const float* __restrict__ bh1,
            const float* __restrict__ Wh2,   const float* __restrict__ bh2)
{
    __shared__ float hbuf[DD], scr[DD], wsum[10], wsq[10], red[2];
    const int b = blockIdx.x, tid = threadIdx.x;
    const float* xr = X + (size_t)b * SS * DD;

    float v = xr[tid];
    float sum = v, sq = v * v;
    #pragma unroll
    for (int o = 16; o > 0; o >>= 1) {
        sum += __shfl_xor_sync(0xffffffffu, sum, o);
        sq  += __shfl_xor_sync(0xffffffffu, sq, o);
    }
    int wid = tid >> 5, lane = tid & 31;
    if (lane == 0) { wsum[wid] = sum; wsq[wid] = sq; }
    __syncthreads();
    if (tid == 0) {
        float s = 0.f, q = 0.f;
        #pragma unroll
        for (int w = 0; w < 10; w++) { s += wsum[w]; q += wsq[w]; }
        float mean = s * (1.f / DD);
        float var  = q * (1.f / DD) - mean * mean;
        red[0] = mean; red[1] = rsqrtf(var + 1e-5f);
    }
    __syncthreads();
    hbuf[tid] = (v - red[0]) * red[1] * hln_w[tid] + hln_b[tid];
    __syncthreads();

    {
        const float4* Wr = (const float4*)(Wh1 + (size_t)tid * DD);
        float acc = 0.f;
        #pragma unroll 4
        for (int k4 = 0; k4 < DD / 4; k4++) {
            float4 w = Wr[k4];
            float4 a = ((const float4*)hbuf)[k4];
            acc += a.x * w.x + a.y * w.y + a.z * w.z + a.w * w.w;
        }
        acc += bh1[tid];
        scr[tid] = 0.5f * acc * (1.f + erff(acc * 0.70710678118654752f));
    }
    __syncthreads();

    if (tid < NM) {
        const float4* Wr = (const float4*)(Wh2 + (size_t)tid * DD);
        float acc = 0.f;
        #pragma unroll 4
        for (int k4 = 0; k4 < DD / 4; k4++) {
            float4 w = Wr[k4];
            float4 a = ((const float4*)scr)[k4];
            acc += a.x * w.x + a.y * w.y + a.z * w.z + a.w * w.w;
        }
        g_c[b * NM + tid] = acc + bh2[tid];
    }
}

__global__ void __launch_bounds__(256)
cheb_kernel(const float* __restrict__ k_norm, float* __restrict__ out)
{
    __shared__ float c[NM];
    const int b = blockIdx.x >> 1;
    const int t = ((blockIdx.x & 1) << 8) + threadIdx.x;
    if (threadIdx.x < NM) c[threadIdx.x] = g_c[b * NM + threadIdx.x];
    __syncthreads();
    float xx = k_norm[b * TT + t];
    float tp = 1.f, tc = xx;
    float acc = c[0] + c[1] * xx;
    float x2 = 2.f * xx;
    #pragma unroll
    for (int n = 2; n < NM; n++) {
        float tn = x2 * tc - tp;
        acc += c[n] * tn;
        tp = tc; tc = tn;
    }
    out[b * TT + t] = 1.f / (1.f + expf(-acc));
}

// ------------------------------------------------------------------
// Host
// ------------------------------------------------------------------
extern "C" void kernel_launch(void* const* d_in, const int* in_sizes, int n_in,
                              void* d_out, int out_size)
{
    const float* k_norm = (const float*)d_in[0];
    const float* ctx    = (const float*)d_in[1];
    const float* W_e    = (const float*)d_in[2];
    const float* b_e    = (const float*)d_in[3];
    const float* cls    = (const float*)d_in[4];
    const float* ln1_w  = (const float*)d_in[5];
    const float* ln1_b  = (const float*)d_in[6];
    const float* W_in   = (const float*)d_in[7];
    const float* b_in   = (const float*)d_in[8];
    const float* W_out  = (const float*)d_in[9];
    const float* b_out  = (const float*)d_in[10];
    const float* ln2_w  = (const float*)d_in[11];
    const float* ln2_b  = (const float*)d_in[12];
    const float* W1     = (const float*)d_in[13];
    const float* b1     = (const float*)d_in[14];
    const float* W2     = (const float*)d_in[15];
    const float* b2     = (const float*)d_in[16];
    const float* hln_w  = (const float*)d_in[17];
    const float* hln_b  = (const float*)d_in[18];
    const float* Wh1    = (const float*)d_in[19];
    const float* bh1    = (const float*)d_in[20];
    const float* Wh2    = (const float*)d_in[21];
    const float* bh2    = (const float*)d_in[22];

    float *px;
    __half *phh, *pqkv, *pbh, *pwh;
    cudaGetSymbolAddress((void**)&px,   g_x);
    cudaGetSymbolAddress((void**)&phh,  g_hh);
    cudaGetSymbolAddress((void**)&pqkv, g_qkv);
    cudaGetSymbolAddress((void**)&pbh,  g_bh);
    cudaGetSymbolAddress((void**)&pwh,  g_wh);

    cudaFuncSetAttribute((void*)gemm_h<0,0,__half>, cudaFuncAttributeMaxDynamicSharedMemorySize, GSM_BYTES);
    cudaFuncSetAttribute((void*)gemm_h<0,1,float>,  cudaFuncAttributeMaxDynamicSharedMemorySize, GSM_BYTES);
    cudaFuncSetAttribute((void*)gemm_h<1,0,__half>, cudaFuncAttributeMaxDynamicSharedMemorySize, GSM_BYTES);
    cudaFuncSetAttribute((void*)attn_kernel,        cudaFuncAttributeMaxDynamicSharedMemorySize, ATTN_SMEM);

    // weight conversion (fp16), once per replay
    conv_h<<<(LL*3*DD*DD + 255)/256, 256>>>(W_in,  pwh + WR_WIN,  LL*3*DD*DD);
    conv_h<<<(LL*DD*DD   + 255)/256, 256>>>(W_out, pwh + WR_WOUT, LL*DD*DD);
    conv_h<<<(LL*FFN*DD  + 255)/256, 256>>>(W1,    pwh + WR_W1,   LL*FFN*DD);
    conv_h<<<(LL*DD*FFN  + 255)/256, 256>>>(W2,    pwh + WR_W2,   LL*DD*FFN);

    embed_kernel<<<MTOT * DD / 256, 256>>>(ctx, W_e, b_e, cls, px);

    for (int l = 0; l < LL; l++) {
        ln_kernel<<<MTOT / 8, 256>>>(px, ln1_w + l * DD, ln1_b + l * DD, phh);
        gemm_h<0,0,__half><<<dim3(MTOT / BM, 960 / BN), 256, GSM_BYTES>>>(
            phh, pwh + WR_WIN + (size_t)l * 3 * DD * DD, b_in + l * 3 * DD, nullptr,
            pqkv, DD, 3 * DD);
        attn_kernel<<<BB, 256, ATTN_SMEM>>>(pqkv, phh);
        gemm_h<0,1,float><<<dim3(MTOT / BM, DD / BN), 256, GSM_BYTES>>>(
            phh, pwh + WR_WOUT + (size_t)l * DD * DD, b_out + l * DD, px,
            px, DD, DD);
        ln_kernel<<<MTOT / 8, 256>>>(px, ln2_w + l * DD, ln2_b + l * DD, phh);
        gemm_h<1,0,__half><<<dim3(MTOT / BM, FFN / BN), 256, GSM_BYTES>>>(
            phh, pwh + WR_W1 + (size_t)l * FFN * DD, b1 + l * FFN, nullptr,
            pbh, DD, FFN);
        gemm_h<0,1,float><<<dim3(MTOT / BM, DD / BN), 256, GSM_BYTES>>>(
            pbh, pwh + WR_W2 + (size_t)l * DD * FFN, b2 + l * DD, px,
            px, FFN, DD);
    }

    head_kernel<<<BB, 320>>>(px, hln_w, hln_b, Wh1, bh1, Wh2, bh2);
    cheb_kernel<<<BB * 2, 256>>>(k_norm, (float*)d_out);
}